// round 11
// baseline (speedup 1.0000x reference)
#include <cuda_runtime.h>

#define S 384
#define D 512
#define H 8
#define DK 64
#define OUT_MAIN (S*S*D)   // 75497472

typedef unsigned long long ull;

__device__ __forceinline__ ull ffma2(ull a, ull b, ull c) {
    ull d;
    asm("fma.rn.f32x2 %0, %1, %2, %3;" : "=l"(d) : "l"(a), "l"(b), "l"(c));
    return d;
}
__device__ __forceinline__ ull pk2(float lo, float hi) {
    ull d; asm("mov.b64 %0, {%1, %2};" : "=l"(d) : "f"(lo), "f"(hi)); return d;
}
__device__ __forceinline__ float2 upk2(ull v) {
    float lo, hi; asm("mov.b64 {%0, %1}, %2;" : "=f"(lo), "=f"(hi) : "l"(v));
    return make_float2(lo, hi);
}
__device__ __forceinline__ float4 add4(float4 a, float4 b) {
    return make_float4(a.x+b.x, a.y+b.y, a.z+b.z, a.w+b.w);
}

// ---------------- scratch ----------------
__device__ float g_qkvP[4*3*S*D];    // split-K partials [ks][op][S*D]
__device__ float g_WvoP[2*DK*D];
__device__ float g_MP[2*H*DK*DK];
__device__ float g_bvoP[4*D];
__device__ float g_qkv[3*S*D];       // reduced: q | k | v
__device__ float g_M[H*DK*DK];
__device__ float g_Wvo[DK*D];
__device__ float g_bvo[D];
__device__ float g_wh[H*DK];
__device__ float g_hvo2[S*H*D];      // [t][h][d], pre-scaled by 1/H
__device__ float g_attnT[S*S*H];     // [s][t][h]

// =================================================================
// K1: split-K double-buffered f32x2 GEMM path (frozen from R9/R10)
// =================================================================
__global__ __launch_bounds__(256) void K1(
    const float* __restrict__ x,
    const float* __restrict__ Wq, const float* __restrict__ bq,
    const float* __restrict__ Wk, const float* __restrict__ bk,
    const float* __restrict__ Wv, const float* __restrict__ bv,
    const float* __restrict__ Wqh, const float* __restrict__ Wkh,
    const float* __restrict__ Wvs, const float* __restrict__ bvs,
    const float* __restrict__ bqh, const float* __restrict__ Wo)
{
    __shared__ float sm[6400];
    int b = blockIdx.x;
    int tid = threadIdx.x;

    if (b < 608) {
        const float* Ap; const float* Wp; const float* biasp = 0; float* outp;
        int m0 = 0, n0 = 0, ldo, kbase, nchunks; bool transB = false;
        if (b < 576) {
            int tile = b >> 2; int ks = b & 3;
            int op = tile / 48, r = tile % 48;
            m0 = (r % 6) * 64; n0 = (r / 6) * 64;
            Ap = x;
            if (op == 0)      { Wp = Wq; biasp = bq; }
            else if (op == 1) { Wp = Wk; biasp = bk; }
            else              { Wp = Wv; biasp = bv; }
            if (ks) biasp = 0;
            outp = g_qkvP + (ks * 3 + op) * S * D;
            ldo = D; kbase = ks * 128; nchunks = 8;
        } else if (b < 592) {
            int nt = (b - 576) >> 1; int ks = (b - 576) & 1;
            n0 = nt * 64;
            Ap = Wvs; Wp = Wo; outp = g_WvoP + ks * DK * D; ldo = D;
            kbase = ks * 256; nchunks = 16;
        } else {
            int h = (b - 592) >> 1; int ks = (b - 592) & 1;
            Ap = Wqh + h * DK * D; Wp = Wkh + h * DK * D;
            outp = g_MP + ks * H * DK * DK + h * DK * DK; ldo = DK; transB = true;
            kbase = ks * 256; nchunks = 16;
        }

        float* sA = sm;          // [2][16][132] duplicated pairs
        float* sB = sm + 4224;   // [2][16][68]

        int ma  = tid >> 2, ka4 = (tid & 3) * 4;
        int kb  = tid >> 4, nb4 = (tid & 15) * 4;
        int tm  = (tid >> 4) * 4, tn = (tid & 15) * 4;

        float4 a4 = *(const float4*)(Ap + (m0 + ma) * D + kbase + ka4);
        float4 b4;
        if (!transB) b4 = *(const float4*)(Wp + (kbase + kb) * D + n0 + nb4);
        else         b4 = *(const float4*)(Wp + ma * D + kbase + ka4);

        ull acc[4][2] = {};
        for (int c = 0; c < nchunks; c++) {
            int buf = c & 1;
            float* sAc = sA + buf * 2112;
            float* sBc = sB + buf * 1088;
            {
                *(float2*)&sAc[(ka4+0)*132 + 2*ma] = make_float2(a4.x, a4.x);
                *(float2*)&sAc[(ka4+1)*132 + 2*ma] = make_float2(a4.y, a4.y);
                *(float2*)&sAc[(ka4+2)*132 + 2*ma] = make_float2(a4.z, a4.z);
                *(float2*)&sAc[(ka4+3)*132 + 2*ma] = make_float2(a4.w, a4.w);
                if (!transB) {
                    *(float4*)&sBc[kb*68 + nb4] = b4;
                } else {
                    sBc[(ka4+0)*68 + ma] = b4.x;
                    sBc[(ka4+1)*68 + ma] = b4.y;
                    sBc[(ka4+2)*68 + ma] = b4.z;
                    sBc[(ka4+3)*68 + ma] = b4.w;
                }
            }
            __syncthreads();
            if (c < nchunks - 1) {
                int k0 = kbase + (c + 1) * 16;
                a4 = *(const float4*)(Ap + (m0 + ma) * D + k0 + ka4);
                if (!transB) b4 = *(const float4*)(Wp + (k0 + kb) * D + n0 + nb4);
                else         b4 = *(const float4*)(Wp + ma * D + k0 + ka4);
            }
            #pragma unroll
            for (int k2 = 0; k2 < 16; k2++) {
                ull pb0 = *(const ull*)&sBc[k2*68 + tn];
                ull pb1 = *(const ull*)&sBc[k2*68 + tn + 2];
                ull pa0 = *(const ull*)&sAc[k2*132 + 2*tm];
                ull pa1 = *(const ull*)&sAc[k2*132 + 2*tm + 2];
                ull pa2 = *(const ull*)&sAc[k2*132 + 2*tm + 4];
                ull pa3 = *(const ull*)&sAc[k2*132 + 2*tm + 6];
                acc[0][0] = ffma2(pa0, pb0, acc[0][0]); acc[0][1] = ffma2(pa0, pb1, acc[0][1]);
                acc[1][0] = ffma2(pa1, pb0, acc[1][0]); acc[1][1] = ffma2(pa1, pb1, acc[1][1]);
                acc[2][0] = ffma2(pa2, pb0, acc[2][0]); acc[2][1] = ffma2(pa2, pb1, acc[2][1]);
                acc[3][0] = ffma2(pa3, pb0, acc[3][0]); acc[3][1] = ffma2(pa3, pb1, acc[3][1]);
            }
            __syncthreads();
        }
        float4 bias4 = make_float4(0.f, 0.f, 0.f, 0.f);
        if (biasp) bias4 = *(const float4*)(biasp + n0 + tn);
        #pragma unroll
        for (int i = 0; i < 4; i++) {
            float2 lo = upk2(acc[i][0]), hi = upk2(acc[i][1]);
            float4 o4 = make_float4(lo.x + bias4.x, lo.y + bias4.y,
                                    hi.x + bias4.z, hi.y + bias4.w);
            *(float4*)(outp + (m0 + tm + i) * ldo + n0 + tn) = o4;
        }
    } else if (b < 616) {
        int p = b - 608;
        int ks = p >> 1, nh = p & 1;
        int n = nh * 256 + tid;
        float acc = 0.f;
        int k0 = ks * 128;
        #pragma unroll 8
        for (int k = k0; k < k0 + 128; k++)
            acc += bvs[k] * Wo[k * D + n];
        g_bvoP[ks * D + n] = acc;
    } else {
        int o = (b - 616) * 8 + (tid >> 5);
        int lane = tid & 31;
        int hh = o >> 6, ii = o & 63;
        const float4* a4p = (const float4*)(Wkh + (hh * DK + ii) * D);
        const float4* b4p = (const float4*)(bqh + hh * D);
        float acc = 0.f;
        #pragma unroll
        for (int r2 = 0; r2 < 4; r2++) {
            float4 av = a4p[lane + 32*r2], bv2 = b4p[lane + 32*r2];
            acc += av.x*bv2.x + av.y*bv2.y + av.z*bv2.z + av.w*bv2.w;
        }
        #pragma unroll
        for (int off = 16; off; off >>= 1)
            acc += __shfl_xor_sync(0xffffffffu, acc, off);
        if (lane == 0) g_wh[o] = acc;
    }
}

// =================================================================
// K1r: reduce split-K partials once (frozen)
// =================================================================
__global__ __launch_bounds__(256) void K1r() {
    int idx = blockIdx.x * 256 + threadIdx.x;
    if (idx < 147456) {
        float4 s = ((const float4*)g_qkvP)[idx];
        #pragma unroll
        for (int p = 1; p < 4; p++)
            s = add4(s, ((const float4*)g_qkvP)[idx + p * 147456]);
        ((float4*)g_qkv)[idx] = s;
    } else if (idx < 155648) {
        int i = idx - 147456;
        float4 a = ((const float4*)g_MP)[i];
        float4 b = ((const float4*)g_MP)[i + 8192];
        ((float4*)g_M)[i] = add4(a, b);
    } else if (idx < 163840) {
        int i = idx - 155648;
        float4 a = ((const float4*)g_WvoP)[i];
        float4 b = ((const float4*)g_WvoP)[i + 8192];
        ((float4*)g_Wvo)[i] = add4(a, b);
    } else if (idx < 163968) {
        int i = idx - 163840;
        float4 s = make_float4(0.f, 0.f, 0.f, 0.f);
        #pragma unroll
        for (int p = 0; p < 4; p++)
            s = add4(s, ((const float4*)g_bvoP)[p * 128 + i]);
        ((float4*)g_bvo)[i] = s;
    }
}

// =================================================================
// K2: fused { attn+softmax, 32-s tiles (0..95) | hvo (96..479) }
// attention: 256 thr = 32 sg x 8 tg; thread owns 8 t per 64-chunk.
// =================================================================
__global__ __launch_bounds__(256) void K2(float* __restrict__ d_out, long long osz) {
    __shared__ float sm[8736];
    int b = blockIdx.x;
    int tid = threadIdx.x;

    const float* gq = g_qkv;
    const float* gk = g_qkv + S*D;
    const float* gv = g_qkv + 2*S*D;

    if (b < 96) {
        int h = b / 12;
        int s0 = (b % 12) * 32;
        float* sKT = sm;             // [64][68] (M in prologue, then K^T)
        float* sQp = sm + 4352;      // [32][68]
        float* sQ  = sm + 6528;      // [32][65]
        float* swh = sm + 8608;      // [64]
        float* sBt = sm + 8672;      // [64]

        // prologue: M -> sKT, q rows -> sQ, wh
        #pragma unroll
        for (int r = 0; r < 4; r++) {
            int lin = (r * 256 + tid) * 4;
            int row = lin >> 6, col = lin & 63;
            float4 m4 = *(const float4*)(g_M + h * DK * DK + lin);
            sKT[row*68+col] = m4.x; sKT[row*68+col+1] = m4.y;
            sKT[row*68+col+2] = m4.z; sKT[row*68+col+3] = m4.w;
        }
        #pragma unroll
        for (int r = 0; r < 2; r++) {
            int lin = (r * 256 + tid) * 4;
            int row = lin >> 6, col = lin & 63;
            float4 q4 = *(const float4*)(gq + (s0 + row) * D + h * DK + col);
            sQ[row*65+col] = q4.x; sQ[row*65+col+1] = q4.y;
            sQ[row*65+col+2] = q4.z; sQ[row*65+col+3] = q4.w;
        }
        if (tid < 64) swh[tid] = g_wh[h * DK + tid];
        __syncthreads();

        // qp[32][64]: thread (sgq = tid>>3, jg = (tid&7)*8) computes 8 cols
        {
            int sgq = tid >> 3, jg = (tid & 7) * 8;
            float a0=0.f,a1=0.f,a2=0.f,a3=0.f,a4v=0.f,a5=0.f,a6=0.f,a7=0.f;
            #pragma unroll
            for (int i = 0; i < 64; i++) {
                float qv = sQ[sgq*65 + i];
                float4 mA = *(const float4*)&sKT[i*68 + jg];
                float4 mB = *(const float4*)&sKT[i*68 + jg + 4];
                a0 += qv*mA.x; a1 += qv*mA.y; a2 += qv*mA.z; a3 += qv*mA.w;
                a4v += qv*mB.x; a5 += qv*mB.y; a6 += qv*mB.z; a7 += qv*mB.w;
            }
            __syncthreads();   // all M reads done before sKT reuse
            sQp[sgq*68 + jg+0] = a0; sQp[sgq*68 + jg+1] = a1;
            sQp[sgq*68 + jg+2] = a2; sQp[sgq*68 + jg+3] = a3;
            sQp[sgq*68 + jg+4] = a4v; sQp[sgq*68 + jg+5] = a5;
            sQp[sgq*68 + jg+6] = a6; sQp[sgq*68 + jg+7] = a7;
        }

        int sg = tid >> 3, tg = tid & 7;
        int s = s0 + sg;
        int tt = tid & 63, kg = tid >> 6;

        float sc[48];
        for (int c = 0; c < 6; c++) {
            // stage K chunk transposed [k][t]
            #pragma unroll
            for (int r = 0; r < 4; r++) {
                int k0 = kg * 16 + r * 4;
                float4 kv = *(const float4*)(gk + (c*64 + tt) * D + h * DK + k0);
                sKT[(k0+0)*68 + tt] = kv.x;
                sKT[(k0+1)*68 + tt] = kv.y;
                sKT[(k0+2)*68 + tt] = kv.z;
                sKT[(k0+3)*68 + tt] = kv.w;
            }
            __syncthreads();   // staging done; also publishes sQp on c==0
            if (tid < 64) {
                float bt = 0.f;
                #pragma unroll
                for (int k = 0; k < 64; k++) bt += sKT[k*68 + tid] * swh[k];
                sBt[tid] = bt;
            }
            ull acc0 = 0, acc1 = 0, acc2 = 0, acc3 = 0;
            #pragma unroll
            for (int k4 = 0; k4 < 16; k4++) {
                float4 q4 = *(const float4*)&sQp[sg*68 + k4*4];
                float qa[4] = {q4.x, q4.y, q4.z, q4.w};
                #pragma unroll
                for (int kk = 0; kk < 4; kk++) {
                    const float* kr = &sKT[(k4*4+kk)*68 + tg*8];
                    float4 kA = *(const float4*)kr;
                    float4 kB = *(const float4*)(kr + 4);
                    ull qp2 = pk2(qa[kk], qa[kk]);
                    acc0 = ffma2(qp2, pk2(kA.x, kA.y), acc0);
                    acc1 = ffma2(qp2, pk2(kA.z, kA.w), acc1);
                    acc2 = ffma2(qp2, pk2(kB.x, kB.y), acc2);
                    acc3 = ffma2(qp2, pk2(kB.z, kB.w), acc3);
                }
            }
            __syncthreads();   // sBt ready; gates next staging
            float2 v0 = upk2(acc0), v1 = upk2(acc1);
            float2 v2 = upk2(acc2), v3 = upk2(acc3);
            int tb = tg * 8;
            sc[c*8+0] = (v0.x + sBt[tb+0]) * 0.125f;
            sc[c*8+1] = (v0.y + sBt[tb+1]) * 0.125f;
            sc[c*8+2] = (v1.x + sBt[tb+2]) * 0.125f;
            sc[c*8+3] = (v1.y + sBt[tb+3]) * 0.125f;
            sc[c*8+4] = (v2.x + sBt[tb+4]) * 0.125f;
            sc[c*8+5] = (v2.y + sBt[tb+5]) * 0.125f;
            sc[c*8+6] = (v3.x + sBt[tb+6]) * 0.125f;
            sc[c*8+7] = (v3.y + sBt[tb+7]) * 0.125f;
        }

        // softmax: row s spread over 8 tg lanes (lane bits 0..2)
        float mx = -1e30f;
        #pragma unroll
        for (int i = 0; i < 48; i++) mx = fmaxf(mx, sc[i]);
        #pragma unroll
        for (int o = 1; o < 8; o <<= 1) mx = fmaxf(mx, __shfl_xor_sync(0xffffffffu, mx, o));
        float sum = 0.f;
        #pragma unroll
        for (int i = 0; i < 48; i++) { sc[i] = __expf(sc[i] - mx); sum += sc[i]; }
        #pragma unroll
        for (int o = 1; o < 8; o <<= 1) sum += __shfl_xor_sync(0xffffffffu, sum, o);
        float inv = 1.0f / sum;

        #pragma unroll
        for (int c = 0; c < 6; c++) {
            int t = c*64 + tg*8;
            float a0 = sc[c*8+0]*inv, a1 = sc[c*8+1]*inv;
            float a2 = sc[c*8+2]*inv, a3 = sc[c*8+3]*inv;
            float a4v = sc[c*8+4]*inv, a5 = sc[c*8+5]*inv;
            float a6 = sc[c*8+6]*inv, a7 = sc[c*8+7]*inv;
            long long base = ((long long)s * S + t) * H + h;
            g_attnT[base + 0*H] = a0; g_attnT[base + 1*H] = a1;
            g_attnT[base + 2*H] = a2; g_attnT[base + 3*H] = a3;
            g_attnT[base + 4*H] = a4v; g_attnT[base + 5*H] = a5;
            g_attnT[base + 6*H] = a6; g_attnT[base + 7*H] = a7;
            if (h == H - 1) {
                long long oi = (long long)OUT_MAIN + (long long)s * S + t;
                if (oi + 7 < osz) {
                    *(float4*)(d_out + oi)     = make_float4(a0, a1, a2, a3);
                    *(float4*)(d_out + oi + 4) = make_float4(a4v, a5, a6, a7);
                }
            }
        }
    } else {
        // ---- hvo2[t][h][:] = (vr @ Wvo + bvo) * (1/H) ----
        int p = b - 96;
        int n0 = (p & 7) * 64;
        int q = p >> 3;
        int h = q / 6, t0 = (q % 6) * 64;
        float* sV = sm;          // [64][65]
        float* sW = sm + 4160;   // [64][68]
        #pragma unroll
        for (int r = 0; r < 4; r++) {
            int lin = tid * 4 + r * 1024;
            int row = lin >> 6, col = lin & 63;
            float4 v4 = *(const float4*)(gv + (t0 + row) * D + h * DK + col);
            sV[row*65+col] = v4.x; sV[row*65+col+1] = v4.y;
            sV[row*65+col+2] = v4.z; sV[row*65+col+3] = v4.w;
            float4 w4 = *(const float4*)(g_Wvo + row * D + n0 + col);
            *(float4*)&sW[row*68+col] = w4;
        }
        __syncthreads();
        int tl = tid >> 2, ng = (tid & 3) * 16;
        ull acc[8];
        {
            float4 b0 = *(const float4*)(g_bvo + n0 + ng);
            float4 b1 = *(const float4*)(g_bvo + n0 + ng + 4);
            float4 b2 = *(const float4*)(g_bvo + n0 + ng + 8);
            float4 b3 = *(const float4*)(g_bvo + n0 + ng + 12);
            acc[0] = pk2(b0.x,b0.y); acc[1] = pk2(b0.z,b0.w);
            acc[2] = pk2(b1.x,b1.y); acc[3] = pk2(b1.z,b1.w);
            acc[4] = pk2(b2.x,b2.y); acc[5] = pk2(b2.z,b2.w);
            acc[6] = pk2(b3.x,b3.y); acc[7] = pk2(b3.z,b3.w);
        }
        #pragma unroll
        for (int i = 0; i < 64; i++) {
            float vv = sV[tl*65 + i];
            ull vp = pk2(vv, vv);
            const float* wr = &sW[i*68 + ng];
            acc[0] = ffma2(vp, *(const ull*)wr,        acc[0]);
            acc[1] = ffma2(vp, *(const ull*)(wr + 2),  acc[1]);
            acc[2] = ffma2(vp, *(const ull*)(wr + 4),  acc[2]);
            acc[3] = ffma2(vp, *(const ull*)(wr + 6),  acc[3]);
            acc[4] = ffma2(vp, *(const ull*)(wr + 8),  acc[4]);
            acc[5] = ffma2(vp, *(const ull*)(wr + 10), acc[5]);
            acc[6] = ffma2(vp, *(const ull*)(wr + 12), acc[6]);
            acc[7] = ffma2(vp, *(const ull*)(wr + 14), acc[7]);
        }
        int t = t0 + tl;
        #pragma unroll
        for (int rq = 0; rq < 4; rq++) {
            float2 lo = upk2(acc[rq*2]), hi = upk2(acc[rq*2+1]);
            float4 o4 = make_float4(lo.x*0.125f, lo.y*0.125f,
                                    hi.x*0.125f, hi.y*0.125f);
            *(float4*)(g_hvo2 + (t * H + h) * D + n0 + ng + rq*4) = o4;
        }
    }
}

// =================================================================
// K4: out[s,t,:] = bo + sum_h attnT[s,t,h] * hvo2[t,h,:] (frozen)
// =================================================================
__global__ __launch_bounds__(256, 4) void K4(float* __restrict__ d_out,
                                             const float* __restrict__ bo,
                                             long long osz) {
    __shared__ float sA[32*2*8];   // [s][t][h] = 512 floats
    int b = blockIdx.x;
    int t0 = (b % 192) * 2;
    int s0 = (b / 192) * 96;
    int tid = threadIdx.x;
    int dl = (tid & 127) * 4, tq = tid >> 7;
    int t = t0 + tq;

    ull hp[8][2];
    #pragma unroll
    for (int hh = 0; hh < 8; hh++) {
        float4 a = *(const float4*)(g_hvo2 + (t * H + hh) * D + dl);
        hp[hh][0] = pk2(a.x, a.y); hp[hh][1] = pk2(a.z, a.w);
    }
    float4 bA = *(const float4*)(bo + dl);
    ull bop0 = pk2(bA.x, bA.y), bop1 = pk2(bA.z, bA.w);

    for (int ch = 0; ch < 3; ch++) {
        int sb = s0 + ch * 32;
        if (tid < 128) {    // stage attn [32 s][2 t][8 h] = 128 float4
            int s = tid >> 2, rem = tid & 3;
            int tt2 = rem >> 1, half = rem & 1;
            *(float4*)&sA[s*16 + tt2*8 + half*4] =
                *(const float4*)(g_attnT + ((long long)(sb+s)*S + t0+tt2)*H + half*4);
        }
        __syncthreads();
        long long oi = ((long long)sb * S + t) * D + dl;
        #pragma unroll 4
        for (int s = 0; s < 32; s++) {
            const float* wb = &sA[s*16 + tq*8];
            float4 wa = *(const float4*)wb;
            float4 wc = *(const float4*)(wb + 4);
            ull w0 = pk2(wa.x,wa.x), w1 = pk2(wa.y,wa.y);
            ull w2 = pk2(wa.z,wa.z), w3 = pk2(wa.w,wa.w);
            ull w4 = pk2(wc.x,wc.x), w5 = pk2(wc.y,wc.y);
            ull w6 = pk2(wc.z,wc.z), w7 = pk2(wc.w,wc.w);
            ull acc0 = bop0, acc1 = bop1;
            acc0 = ffma2(w0, hp[0][0], acc0); acc1 = ffma2(w0, hp[0][1], acc1);
            acc0 = ffma2(w1, hp[1][0], acc0); acc1 = ffma2(w1, hp[1][1], acc1);
            acc0 = ffma2(w2, hp[2][0], acc0); acc1 = ffma2(w2, hp[2][1], acc1);
            acc0 = ffma2(w3, hp[3][0], acc0); acc1 = ffma2(w3, hp[3][1], acc1);
            acc0 = ffma2(w4, hp[4][0], acc0); acc1 = ffma2(w4, hp[4][1], acc1);
            acc0 = ffma2(w5, hp[5][0], acc0); acc1 = ffma2(w5, hp[5][1], acc1);
            acc0 = ffma2(w6, hp[6][0], acc0); acc1 = ffma2(w6, hp[6][1], acc1);
            acc0 = ffma2(w7, hp[7][0], acc0); acc1 = ffma2(w7, hp[7][1], acc1);
            float2 r0 = upk2(acc0), r1 = upk2(acc1);
            if (oi + 3 < osz)
                __stcs((float4*)(d_out + oi), make_float4(r0.x, r0.y, r1.x, r1.y));
            oi += (long long)S * D;
        }
        __syncthreads();
    }
}

extern "C" void kernel_launch(void* const* d_in, const int* in_sizes, int n_in,
                              void* d_out, int out_size) {
    const float* x   = (const float*)d_in[0];
    const float* Wq  = (const float*)d_in[1];
    const float* bq  = (const float*)d_in[2];
    const float* Wk  = (const float*)d_in[3];
    const float* bk  = (const float*)d_in[4];
    const float* Wv  = (const float*)d_in[5];
    const float* bv  = (const float*)d_in[6];
    const float* Wqh = (const float*)d_in[7];
    const float* bqh = (const float*)d_in[8];
    const float* Wkh = (const float*)d_in[9];
    const float* Wvs = (const float*)d_in[11];
    const float* bvs = (const float*)d_in[12];
    const float* Wo  = (const float*)d_in[13];
    const float* bo  = (const float*)d_in[14];
    float* out = (float*)d_out;
    long long osz = (long long)out_size;

    K1 <<<624, 256>>>(x, Wq, bq, Wk, bk, Wv, bv, Wqh, Wkh, Wvs, bvs, bqh, Wo);
    K1r<<<641, 256>>>();
    K2 <<<480, 256>>>(out, osz);
    K4 <<<768, 256>>>(out, bo, osz);
}

// round 12
// speedup vs baseline: 1.0746x; 1.0746x over previous
#include <cuda_runtime.h>

#define S 384
#define D 512
#define H 8
#define DK 64
#define OUT_MAIN (S*S*D)   // 75497472

typedef unsigned long long ull;

__device__ __forceinline__ ull ffma2(ull a, ull b, ull c) {
    ull d;
    asm("fma.rn.f32x2 %0, %1, %2, %3;" : "=l"(d) : "l"(a), "l"(b), "l"(c));
    return d;
}
__device__ __forceinline__ ull pk2(float lo, float hi) {
    ull d; asm("mov.b64 %0, {%1, %2};" : "=l"(d) : "f"(lo), "f"(hi)); return d;
}
__device__ __forceinline__ float2 upk2(ull v) {
    float lo, hi; asm("mov.b64 {%0, %1}, %2;" : "=f"(lo), "=f"(hi) : "l"(v));
    return make_float2(lo, hi);
}
__device__ __forceinline__ float4 add4(float4 a, float4 b) {
    return make_float4(a.x+b.x, a.y+b.y, a.z+b.z, a.w+b.w);
}

// ---------------- scratch ----------------
__device__ float g_qkvP[4*3*S*D];    // split-K partials [ks][op][S*D]
__device__ float g_WvoP[2*DK*D];
__device__ float g_MP[2*H*DK*DK];
__device__ float g_bvoP[4*D];
__device__ float g_qkv[3*S*D];       // reduced: q | k | v
__device__ float g_M[H*DK*DK];
__device__ float g_Wvo[DK*D];
__device__ float g_bvo[D];
__device__ float g_wh[H*DK];
__device__ float g_hvo2[S*H*D];      // [t][h][d], pre-scaled by 1/H
__device__ float g_attnT[S*S*H];     // [s][t][h]

// =================================================================
// K1: split-K double-buffered f32x2 GEMM path (frozen)
// =================================================================
__global__ __launch_bounds__(256) void K1(
    const float* __restrict__ x,
    const float* __restrict__ Wq, const float* __restrict__ bq,
    const float* __restrict__ Wk, const float* __restrict__ bk,
    const float* __restrict__ Wv, const float* __restrict__ bv,
    const float* __restrict__ Wqh, const float* __restrict__ Wkh,
    const float* __restrict__ Wvs, const float* __restrict__ bvs,
    const float* __restrict__ bqh, const float* __restrict__ Wo)
{
    __shared__ float sm[6400];
    int b = blockIdx.x;
    int tid = threadIdx.x;

    if (b < 608) {
        const float* Ap; const float* Wp; const float* biasp = 0; float* outp;
        int m0 = 0, n0 = 0, ldo, kbase, nchunks; bool transB = false;
        if (b < 576) {
            int tile = b >> 2; int ks = b & 3;
            int op = tile / 48, r = tile % 48;
            m0 = (r % 6) * 64; n0 = (r / 6) * 64;
            Ap = x;
            if (op == 0)      { Wp = Wq; biasp = bq; }
            else if (op == 1) { Wp = Wk; biasp = bk; }
            else              { Wp = Wv; biasp = bv; }
            if (ks) biasp = 0;
            outp = g_qkvP + (ks * 3 + op) * S * D;
            ldo = D; kbase = ks * 128; nchunks = 8;
        } else if (b < 592) {
            int nt = (b - 576) >> 1; int ks = (b - 576) & 1;
            n0 = nt * 64;
            Ap = Wvs; Wp = Wo; outp = g_WvoP + ks * DK * D; ldo = D;
            kbase = ks * 256; nchunks = 16;
        } else {
            int h = (b - 592) >> 1; int ks = (b - 592) & 1;
            Ap = Wqh + h * DK * D; Wp = Wkh + h * DK * D;
            outp = g_MP + ks * H * DK * DK + h * DK * DK; ldo = DK; transB = true;
            kbase = ks * 256; nchunks = 16;
        }

        float* sA = sm;          // [2][16][132] duplicated pairs
        float* sB = sm + 4224;   // [2][16][68]

        int ma  = tid >> 2, ka4 = (tid & 3) * 4;
        int kb  = tid >> 4, nb4 = (tid & 15) * 4;
        int tm  = (tid >> 4) * 4, tn = (tid & 15) * 4;

        float4 a4 = *(const float4*)(Ap + (m0 + ma) * D + kbase + ka4);
        float4 b4;
        if (!transB) b4 = *(const float4*)(Wp + (kbase + kb) * D + n0 + nb4);
        else         b4 = *(const float4*)(Wp + ma * D + kbase + ka4);

        ull acc[4][2] = {};
        for (int c = 0; c < nchunks; c++) {
            int buf = c & 1;
            float* sAc = sA + buf * 2112;
            float* sBc = sB + buf * 1088;
            {
                *(float2*)&sAc[(ka4+0)*132 + 2*ma] = make_float2(a4.x, a4.x);
                *(float2*)&sAc[(ka4+1)*132 + 2*ma] = make_float2(a4.y, a4.y);
                *(float2*)&sAc[(ka4+2)*132 + 2*ma] = make_float2(a4.z, a4.z);
                *(float2*)&sAc[(ka4+3)*132 + 2*ma] = make_float2(a4.w, a4.w);
                if (!transB) {
                    *(float4*)&sBc[kb*68 + nb4] = b4;
                } else {
                    sBc[(ka4+0)*68 + ma] = b4.x;
                    sBc[(ka4+1)*68 + ma] = b4.y;
                    sBc[(ka4+2)*68 + ma] = b4.z;
                    sBc[(ka4+3)*68 + ma] = b4.w;
                }
            }
            __syncthreads();
            if (c < nchunks - 1) {
                int k0 = kbase + (c + 1) * 16;
                a4 = *(const float4*)(Ap + (m0 + ma) * D + k0 + ka4);
                if (!transB) b4 = *(const float4*)(Wp + (k0 + kb) * D + n0 + nb4);
                else         b4 = *(const float4*)(Wp + ma * D + k0 + ka4);
            }
            #pragma unroll
            for (int k2 = 0; k2 < 16; k2++) {
                ull pb0 = *(const ull*)&sBc[k2*68 + tn];
                ull pb1 = *(const ull*)&sBc[k2*68 + tn + 2];
                ull pa0 = *(const ull*)&sAc[k2*132 + 2*tm];
                ull pa1 = *(const ull*)&sAc[k2*132 + 2*tm + 2];
                ull pa2 = *(const ull*)&sAc[k2*132 + 2*tm + 4];
                ull pa3 = *(const ull*)&sAc[k2*132 + 2*tm + 6];
                acc[0][0] = ffma2(pa0, pb0, acc[0][0]); acc[0][1] = ffma2(pa0, pb1, acc[0][1]);
                acc[1][0] = ffma2(pa1, pb0, acc[1][0]); acc[1][1] = ffma2(pa1, pb1, acc[1][1]);
                acc[2][0] = ffma2(pa2, pb0, acc[2][0]); acc[2][1] = ffma2(pa2, pb1, acc[2][1]);
                acc[3][0] = ffma2(pa3, pb0, acc[3][0]); acc[3][1] = ffma2(pa3, pb1, acc[3][1]);
            }
            __syncthreads();
        }
        float4 bias4 = make_float4(0.f, 0.f, 0.f, 0.f);
        if (biasp) bias4 = *(const float4*)(biasp + n0 + tn);
        #pragma unroll
        for (int i = 0; i < 4; i++) {
            float2 lo = upk2(acc[i][0]), hi = upk2(acc[i][1]);
            float4 o4 = make_float4(lo.x + bias4.x, lo.y + bias4.y,
                                    hi.x + bias4.z, hi.y + bias4.w);
            *(float4*)(outp + (m0 + tm + i) * ldo + n0 + tn) = o4;
        }
    } else if (b < 616) {
        int p = b - 608;
        int ks = p >> 1, nh = p & 1;
        int n = nh * 256 + tid;
        float acc = 0.f;
        int k0 = ks * 128;
        #pragma unroll 8
        for (int k = k0; k < k0 + 128; k++)
            acc += bvs[k] * Wo[k * D + n];
        g_bvoP[ks * D + n] = acc;
    } else {
        int o = (b - 616) * 8 + (tid >> 5);
        int lane = tid & 31;
        int hh = o >> 6, ii = o & 63;
        const float4* a4p = (const float4*)(Wkh + (hh * DK + ii) * D);
        const float4* b4p = (const float4*)(bqh + hh * D);
        float acc = 0.f;
        #pragma unroll
        for (int r2 = 0; r2 < 4; r2++) {
            float4 av = a4p[lane + 32*r2], bv2 = b4p[lane + 32*r2];
            acc += av.x*bv2.x + av.y*bv2.y + av.z*bv2.z + av.w*bv2.w;
        }
        #pragma unroll
        for (int off = 16; off; off >>= 1)
            acc += __shfl_xor_sync(0xffffffffu, acc, off);
        if (lane == 0) g_wh[o] = acc;
    }
}

// =================================================================
// K1r: reduce split-K partials once (frozen)
// =================================================================
__global__ __launch_bounds__(256) void K1r() {
    int idx = blockIdx.x * 256 + threadIdx.x;
    if (idx < 147456) {
        float4 s = ((const float4*)g_qkvP)[idx];
        #pragma unroll
        for (int p = 1; p < 4; p++)
            s = add4(s, ((const float4*)g_qkvP)[idx + p * 147456]);
        ((float4*)g_qkv)[idx] = s;
    } else if (idx < 155648) {
        int i = idx - 147456;
        float4 a = ((const float4*)g_MP)[i];
        float4 b = ((const float4*)g_MP)[i + 8192];
        ((float4*)g_M)[i] = add4(a, b);
    } else if (idx < 163840) {
        int i = idx - 155648;
        float4 a = ((const float4*)g_WvoP)[i];
        float4 b = ((const float4*)g_WvoP)[i + 8192];
        ((float4*)g_Wvo)[i] = add4(a, b);
    } else if (idx < 163968) {
        int i = idx - 163840;
        float4 s = make_float4(0.f, 0.f, 0.f, 0.f);
        #pragma unroll
        for (int p = 0; p < 4; p++)
            s = add4(s, ((const float4*)g_bvoP)[p * 128 + i]);
        ((float4*)g_bvo)[i] = s;
    }
}

// =================================================================
// K2: fused { attn+softmax 16-s tiles (0..191) | hvo (192..575) }
// (R10 form; hvo weight loads widened to LDS.128)
// =================================================================
__global__ __launch_bounds__(256) void K2(float* __restrict__ d_out, long long osz) {
    __shared__ float sm[8512];
    int b = blockIdx.x;
    int tid = threadIdx.x;

    const float* gq = g_qkv;
    const float* gk = g_qkv + S*D;
    const float* gv = g_qkv + 2*S*D;

    if (b < 192) {
        int h = b / 24;
        int s0 = (b % 24) * 16;
        float* sKT = sm;             // [64][68]
        float* sQp = sm + 4352;      // [16][68]
        float* sQ  = sm + 5440;      // [16][65]
        float* swh = sm + 6480;      // [64]
        float* sBt = sm + 6544;      // [64]

        #pragma unroll
        for (int r = 0; r < 4; r++) {
            int lin = (r * 256 + tid) * 4;
            int row = lin >> 6, col = lin & 63;
            float4 m4 = *(const float4*)(g_M + h * DK * DK + lin);
            sKT[row*68+col] = m4.x; sKT[row*68+col+1] = m4.y;
            sKT[row*68+col+2] = m4.z; sKT[row*68+col+3] = m4.w;
        }
        {
            int lin = tid * 4;
            int row = lin >> 6, col = lin & 63;
            float4 q4 = *(const float4*)(gq + (s0 + row) * D + h * DK + col);
            sQ[row*65+col] = q4.x; sQ[row*65+col+1] = q4.y;
            sQ[row*65+col+2] = q4.z; sQ[row*65+col+3] = q4.w;
        }
        if (tid < 64) swh[tid] = g_wh[h * DK + tid];
        __syncthreads();

        {
            int sgq = tid >> 4, jg = (tid & 15) * 4;
            float a0 = 0.f, a1 = 0.f, a2 = 0.f, a3 = 0.f;
            #pragma unroll
            for (int i = 0; i < 64; i++) {
                float qv = sQ[sgq*65 + i];
                float4 m4 = *(const float4*)&sKT[i*68 + jg];
                a0 += qv*m4.x; a1 += qv*m4.y; a2 += qv*m4.z; a3 += qv*m4.w;
            }
            __syncthreads();
            sQp[sgq*68 + jg+0] = a0; sQp[sgq*68 + jg+1] = a1;
            sQp[sgq*68 + jg+2] = a2; sQp[sgq*68 + jg+3] = a3;
        }
        __syncthreads();

        int sg = tid >> 4, tg = tid & 15;
        int s = s0 + sg;
        int tt = tid & 63, kg = tid >> 6;

        float sc[24];
        for (int c = 0; c < 6; c++) {
            #pragma unroll
            for (int r = 0; r < 4; r++) {
                int k0 = kg * 16 + r * 4;
                float4 kv = *(const float4*)(gk + (c*64 + tt) * D + h * DK + k0);
                sKT[(k0+0)*68 + tt] = kv.x;
                sKT[(k0+1)*68 + tt] = kv.y;
                sKT[(k0+2)*68 + tt] = kv.z;
                sKT[(k0+3)*68 + tt] = kv.w;
            }
            __syncthreads();
            if (tid < 64) {
                float bt = 0.f;
                #pragma unroll
                for (int k = 0; k < 64; k++) bt += sKT[k*68 + tid] * swh[k];
                sBt[tid] = bt;
            }
            ull acc0 = 0, acc1 = 0;
            #pragma unroll
            for (int k4 = 0; k4 < 16; k4++) {
                float4 q4 = *(const float4*)&sQp[sg*68 + k4*4];
                float qa[4] = {q4.x, q4.y, q4.z, q4.w};
                #pragma unroll
                for (int kk = 0; kk < 4; kk++) {
                    float4 kv = *(const float4*)&sKT[(k4*4+kk)*68 + tg*4];
                    ull kA = pk2(kv.x, kv.y), kB = pk2(kv.z, kv.w);
                    ull qp2 = pk2(qa[kk], qa[kk]);
                    acc0 = ffma2(qp2, kA, acc0);
                    acc1 = ffma2(qp2, kB, acc1);
                }
            }
            __syncthreads();
            float2 v0 = upk2(acc0), v1 = upk2(acc1);
            int tb = tg * 4;
            sc[c*4+0] = (v0.x + sBt[tb+0]) * 0.125f;
            sc[c*4+1] = (v0.y + sBt[tb+1]) * 0.125f;
            sc[c*4+2] = (v1.x + sBt[tb+2]) * 0.125f;
            sc[c*4+3] = (v1.y + sBt[tb+3]) * 0.125f;
        }

        float mx = -1e30f;
        #pragma unroll
        for (int i = 0; i < 24; i++) mx = fmaxf(mx, sc[i]);
        #pragma unroll
        for (int o = 1; o < 16; o <<= 1) mx = fmaxf(mx, __shfl_xor_sync(0xffffffffu, mx, o));
        float sum = 0.f;
        #pragma unroll
        for (int i = 0; i < 24; i++) { sc[i] = __expf(sc[i] - mx); sum += sc[i]; }
        #pragma unroll
        for (int o = 1; o < 16; o <<= 1) sum += __shfl_xor_sync(0xffffffffu, sum, o);
        float inv = 1.0f / sum;

        #pragma unroll
        for (int c = 0; c < 6; c++) {
            float a0 = sc[c*4+0] * inv;
            float a1 = sc[c*4+1] * inv;
            float a2 = sc[c*4+2] * inv;
            float a3 = sc[c*4+3] * inv;
            int t = c*64 + tg*4;
            g_attnT[((long long)s * S + t + 0) * H + h] = a0;
            g_attnT[((long long)s * S + t + 1) * H + h] = a1;
            g_attnT[((long long)s * S + t + 2) * H + h] = a2;
            g_attnT[((long long)s * S + t + 3) * H + h] = a3;
            if (h == H - 1) {
                long long oi = (long long)OUT_MAIN + (long long)s * S + t;
                if (oi + 3 < osz)
                    *(float4*)(d_out + oi) = make_float4(a0, a1, a2, a3);
            }
        }
    } else {
        // ---- hvo2[t][h][:] = (vr @ Wvo + bvo) * (1/H) ----
        int p = b - 192;
        int n0 = (p & 7) * 64;
        int q = p >> 3;
        int h = q / 6, t0 = (q % 6) * 64;
        float* sV = sm;          // [64][65]
        float* sW = sm + 4160;   // [64][68]
        #pragma unroll
        for (int r = 0; r < 4; r++) {
            int lin = tid * 4 + r * 1024;
            int row = lin >> 6, col = lin & 63;
            float4 v4 = *(const float4*)(gv + (t0 + row) * D + h * DK + col);
            sV[row*65+col] = v4.x; sV[row*65+col+1] = v4.y;
            sV[row*65+col+2] = v4.z; sV[row*65+col+3] = v4.w;
            float4 w4 = *(const float4*)(g_Wvo + row * D + n0 + col);
            *(float4*)&sW[row*68+col] = w4;
        }
        __syncthreads();
        int tl = tid >> 2, ng = (tid & 3) * 16;
        ull acc[8];
        {
            float4 b0 = *(const float4*)(g_bvo + n0 + ng);
            float4 b1 = *(const float4*)(g_bvo + n0 + ng + 4);
            float4 b2 = *(const float4*)(g_bvo + n0 + ng + 8);
            float4 b3 = *(const float4*)(g_bvo + n0 + ng + 12);
            acc[0] = pk2(b0.x,b0.y); acc[1] = pk2(b0.z,b0.w);
            acc[2] = pk2(b1.x,b1.y); acc[3] = pk2(b1.z,b1.w);
            acc[4] = pk2(b2.x,b2.y); acc[5] = pk2(b2.z,b2.w);
            acc[6] = pk2(b3.x,b3.y); acc[7] = pk2(b3.z,b3.w);
        }
        #pragma unroll
        for (int i = 0; i < 64; i++) {
            float vv = sV[tl*65 + i];
            ull vp = pk2(vv, vv);
            const float* wr = &sW[i*68 + ng];
            float4 wA = *(const float4*)wr;
            float4 wB = *(const float4*)(wr + 4);
            float4 wC = *(const float4*)(wr + 8);
            float4 wD = *(const float4*)(wr + 12);
            acc[0] = ffma2(vp, pk2(wA.x, wA.y), acc[0]);
            acc[1] = ffma2(vp, pk2(wA.z, wA.w), acc[1]);
            acc[2] = ffma2(vp, pk2(wB.x, wB.y), acc[2]);
            acc[3] = ffma2(vp, pk2(wB.z, wB.w), acc[3]);
            acc[4] = ffma2(vp, pk2(wC.x, wC.y), acc[4]);
            acc[5] = ffma2(vp, pk2(wC.z, wC.w), acc[5]);
            acc[6] = ffma2(vp, pk2(wD.x, wD.y), acc[6]);
            acc[7] = ffma2(vp, pk2(wD.z, wD.w), acc[7]);
        }
        int t = t0 + tl;
        #pragma unroll
        for (int rq = 0; rq < 4; rq++) {
            float2 lo = upk2(acc[rq*2]), hi = upk2(acc[rq*2+1]);
            float4 o4 = make_float4(lo.x*0.125f, lo.y*0.125f,
                                    hi.x*0.125f, hi.y*0.125f);
            *(float4*)(g_hvo2 + (t * H + h) * D + n0 + ng + rq*4) = o4;
        }
    }
}

// =================================================================
// K4: out[s,t,:] = bo + sum_h attnT[s,t,h] * hvo2[t,h,:] (frozen)
// =================================================================
__global__ __launch_bounds__(256, 4) void K4(float* __restrict__ d_out,
                                             const float* __restrict__ bo,
                                             long long osz) {
    __shared__ float sA[32*2*8];   // [s][t][h] = 512 floats
    int b = blockIdx.x;
    int t0 = (b % 192) * 2;
    int s0 = (b / 192) * 96;
    int tid = threadIdx.x;
    int dl = (tid & 127) * 4, tq = tid >> 7;
    int t = t0 + tq;

    ull hp[8][2];
    #pragma unroll
    for (int hh = 0; hh < 8; hh++) {
        float4 a = *(const float4*)(g_hvo2 + (t * H + hh) * D + dl);
        hp[hh][0] = pk2(a.x, a.y); hp[hh][1] = pk2(a.z, a.w);
    }
    float4 bA = *(const float4*)(bo + dl);
    ull bop0 = pk2(bA.x, bA.y), bop1 = pk2(bA.z, bA.w);

    for (int ch = 0; ch < 3; ch++) {
        int sb = s0 + ch * 32;
        if (tid < 128) {    // stage attn [32 s][2 t][8 h] = 128 float4
            int s = tid >> 2, rem = tid & 3;
            int tt2 = rem >> 1, half = rem & 1;
            *(float4*)&sA[s*16 + tt2*8 + half*4] =
                *(const float4*)(g_attnT + ((long long)(sb+s)*S + t0+tt2)*H + half*4);
        }
        __syncthreads();
        long long oi = ((long long)sb * S + t) * D + dl;
        #pragma unroll 4
        for (int s = 0; s < 32; s++) {
            const float* wb = &sA[s*16 + tq*8];
            float4 wa = *(const float4*)wb;
            float4 wc = *(const float4*)(wb + 4);
            ull w0 = pk2(wa.x,wa.x), w1 = pk2(wa.y,wa.y);
            ull w2 = pk2(wa.z,wa.z), w3 = pk2(wa.w,wa.w);
            ull w4 = pk2(wc.x,wc.x), w5 = pk2(wc.y,wc.y);
            ull w6 = pk2(wc.z,wc.z), w7 = pk2(wc.w,wc.w);
            ull acc0 = bop0, acc1 = bop1;
            acc0 = ffma2(w0, hp[0][0], acc0); acc1 = ffma2(w0, hp[0][1], acc1);
            acc0 = ffma2(w1, hp[1][0], acc0); acc1 = ffma2(w1, hp[1][1], acc1);
            acc0 = ffma2(w2, hp[2][0], acc0); acc1 = ffma2(w2, hp[2][1], acc1);
            acc0 = ffma2(w3, hp[3][0], acc0); acc1 = ffma2(w3, hp[3][1], acc1);
            acc0 = ffma2(w4, hp[4][0], acc0); acc1 = ffma2(w4, hp[4][1], acc1);
            acc0 = ffma2(w5, hp[5][0], acc0); acc1 = ffma2(w5, hp[5][1], acc1);
            acc0 = ffma2(w6, hp[6][0], acc0); acc1 = ffma2(w6, hp[6][1], acc1);
            acc0 = ffma2(w7, hp[7][0], acc0); acc1 = ffma2(w7, hp[7][1], acc1);
            float2 r0 = upk2(acc0), r1 = upk2(acc1);
            if (oi + 3 < osz)
                __stcs((float4*)(d_out + oi), make_float4(r0.x, r0.y, r1.x, r1.y));
            oi += (long long)S * D;
        }
        __syncthreads();
    }
}

extern "C" void kernel_launch(void* const* d_in, const int* in_sizes, int n_in,
                              void* d_out, int out_size) {
    const float* x   = (const float*)d_in[0];
    const float* Wq  = (const float*)d_in[1];
    const float* bq  = (const float*)d_in[2];
    const float* Wk  = (const float*)d_in[3];
    const float* bk  = (const float*)d_in[4];
    const float* Wv  = (const float*)d_in[5];
    const float* bv  = (const float*)d_in[6];
    const float* Wqh = (const float*)d_in[7];
    const float* bqh = (const float*)d_in[8];
    const float* Wkh = (const float*)d_in[9];
    const float* Wvs = (const float*)d_in[11];
    const float* bvs = (const float*)d_in[12];
    const float* Wo  = (const float*)d_in[13];
    const float* bo  = (const float*)d_in[14];
    float* out = (float*)d_out;
    long long osz = (long long)out_size;

    K1 <<<624, 256>>>(x, Wq, bq, Wk, bk, Wv, bv, Wqh, Wkh, Wvs, bvs, bqh, Wo);
    K1r<<<641, 256>>>();
    K2 <<<576, 256>>>(out, osz);
    K4 <<<768, 256>>>(out, bo, osz);
}

// round 13
// speedup vs baseline: 1.0840x; 1.0088x over previous
#include <cuda_runtime.h>

#define S 384
#define D 512
#define H 8
#define DK 64
#define OUT_MAIN (S*S*D)   // 75497472

typedef unsigned long long ull;

__device__ __forceinline__ ull ffma2(ull a, ull b, ull c) {
    ull d;
    asm("fma.rn.f32x2 %0, %1, %2, %3;" : "=l"(d) : "l"(a), "l"(b), "l"(c));
    return d;
}
__device__ __forceinline__ ull pk2(float lo, float hi) {
    ull d; asm("mov.b64 %0, {%1, %2};" : "=l"(d) : "f"(lo), "f"(hi)); return d;
}
__device__ __forceinline__ float2 upk2(ull v) {
    float lo, hi; asm("mov.b64 {%0, %1}, %2;" : "=f"(lo), "=f"(hi) : "l"(v));
    return make_float2(lo, hi);
}
__device__ __forceinline__ float4 add4(float4 a, float4 b) {
    return make_float4(a.x+b.x, a.y+b.y, a.z+b.z, a.w+b.w);
}

// ---------------- scratch ----------------
__device__ float g_qkvP[4*3*S*D];    // split-K partials [ks][op][S*D]
__device__ float g_WvoP[2*DK*D];
__device__ float g_MP[2*H*DK*DK];
__device__ float g_bvoP[4*D];
__device__ float g_qkv[3*S*D];       // reduced: q | k | v
__device__ float g_M[H*DK*DK];
__device__ float g_Wvo[DK*D];
__device__ float g_bvo[D];
__device__ float g_wh[H*DK];
__device__ float g_bt[H*S];          // precomputed bterm
__device__ float g_hvo2[S*H*D];      // [t][h][d], pre-scaled by 1/H
__device__ float g_attnT[S*S*H];     // [s][t][h]

// =================================================================
// K1: split-K double-buffered f32x2 GEMM path (frozen)
// =================================================================
__global__ __launch_bounds__(256) void K1(
    const float* __restrict__ x,
    const float* __restrict__ Wq, const float* __restrict__ bq,
    const float* __restrict__ Wk, const float* __restrict__ bk,
    const float* __restrict__ Wv, const float* __restrict__ bv,
    const float* __restrict__ Wqh, const float* __restrict__ Wkh,
    const float* __restrict__ Wvs, const float* __restrict__ bvs,
    const float* __restrict__ bqh, const float* __restrict__ Wo)
{
    __shared__ float sm[6400];
    int b = blockIdx.x;
    int tid = threadIdx.x;

    if (b < 608) {
        const float* Ap; const float* Wp; const float* biasp = 0; float* outp;
        int m0 = 0, n0 = 0, ldo, kbase, nchunks; bool transB = false;
        if (b < 576) {
            int tile = b >> 2; int ks = b & 3;
            int op = tile / 48, r = tile % 48;
            m0 = (r % 6) * 64; n0 = (r / 6) * 64;
            Ap = x;
            if (op == 0)      { Wp = Wq; biasp = bq; }
            else if (op == 1) { Wp = Wk; biasp = bk; }
            else              { Wp = Wv; biasp = bv; }
            if (ks) biasp = 0;
            outp = g_qkvP + (ks * 3 + op) * S * D;
            ldo = D; kbase = ks * 128; nchunks = 8;
        } else if (b < 592) {
            int nt = (b - 576) >> 1; int ks = (b - 576) & 1;
            n0 = nt * 64;
            Ap = Wvs; Wp = Wo; outp = g_WvoP + ks * DK * D; ldo = D;
            kbase = ks * 256; nchunks = 16;
        } else {
            int h = (b - 592) >> 1; int ks = (b - 592) & 1;
            Ap = Wqh + h * DK * D; Wp = Wkh + h * DK * D;
            outp = g_MP + ks * H * DK * DK + h * DK * DK; ldo = DK; transB = true;
            kbase = ks * 256; nchunks = 16;
        }

        float* sA = sm;          // [2][16][132] duplicated pairs
        float* sB = sm + 4224;   // [2][16][68]

        int ma  = tid >> 2, ka4 = (tid & 3) * 4;
        int kb  = tid >> 4, nb4 = (tid & 15) * 4;
        int tm  = (tid >> 4) * 4, tn = (tid & 15) * 4;

        float4 a4 = *(const float4*)(Ap + (m0 + ma) * D + kbase + ka4);
        float4 b4;
        if (!transB) b4 = *(const float4*)(Wp + (kbase + kb) * D + n0 + nb4);
        else         b4 = *(const float4*)(Wp + ma * D + kbase + ka4);

        ull acc[4][2] = {};
        for (int c = 0; c < nchunks; c++) {
            int buf = c & 1;
            float* sAc = sA + buf * 2112;
            float* sBc = sB + buf * 1088;
            {
                *(float2*)&sAc[(ka4+0)*132 + 2*ma] = make_float2(a4.x, a4.x);
                *(float2*)&sAc[(ka4+1)*132 + 2*ma] = make_float2(a4.y, a4.y);
                *(float2*)&sAc[(ka4+2)*132 + 2*ma] = make_float2(a4.z, a4.z);
                *(float2*)&sAc[(ka4+3)*132 + 2*ma] = make_float2(a4.w, a4.w);
                if (!transB) {
                    *(float4*)&sBc[kb*68 + nb4] = b4;
                } else {
                    sBc[(ka4+0)*68 + ma] = b4.x;
                    sBc[(ka4+1)*68 + ma] = b4.y;
                    sBc[(ka4+2)*68 + ma] = b4.z;
                    sBc[(ka4+3)*68 + ma] = b4.w;
                }
            }
            __syncthreads();
            if (c < nchunks - 1) {
                int k0 = kbase + (c + 1) * 16;
                a4 = *(const float4*)(Ap + (m0 + ma) * D + k0 + ka4);
                if (!transB) b4 = *(const float4*)(Wp + (k0 + kb) * D + n0 + nb4);
                else         b4 = *(const float4*)(Wp + ma * D + k0 + ka4);
            }
            #pragma unroll
            for (int k2 = 0; k2 < 16; k2++) {
                ull pb0 = *(const ull*)&sBc[k2*68 + tn];
                ull pb1 = *(const ull*)&sBc[k2*68 + tn + 2];
                ull pa0 = *(const ull*)&sAc[k2*132 + 2*tm];
                ull pa1 = *(const ull*)&sAc[k2*132 + 2*tm + 2];
                ull pa2 = *(const ull*)&sAc[k2*132 + 2*tm + 4];
                ull pa3 = *(const ull*)&sAc[k2*132 + 2*tm + 6];
                acc[0][0] = ffma2(pa0, pb0, acc[0][0]); acc[0][1] = ffma2(pa0, pb1, acc[0][1]);
                acc[1][0] = ffma2(pa1, pb0, acc[1][0]); acc[1][1] = ffma2(pa1, pb1, acc[1][1]);
                acc[2][0] = ffma2(pa2, pb0, acc[2][0]); acc[2][1] = ffma2(pa2, pb1, acc[2][1]);
                acc[3][0] = ffma2(pa3, pb0, acc[3][0]); acc[3][1] = ffma2(pa3, pb1, acc[3][1]);
            }
            __syncthreads();
        }
        float4 bias4 = make_float4(0.f, 0.f, 0.f, 0.f);
        if (biasp) bias4 = *(const float4*)(biasp + n0 + tn);
        #pragma unroll
        for (int i = 0; i < 4; i++) {
            float2 lo = upk2(acc[i][0]), hi = upk2(acc[i][1]);
            float4 o4 = make_float4(lo.x + bias4.x, lo.y + bias4.y,
                                    hi.x + bias4.z, hi.y + bias4.w);
            *(float4*)(outp + (m0 + tm + i) * ldo + n0 + tn) = o4;
        }
    } else if (b < 616) {
        int p = b - 608;
        int ks = p >> 1, nh = p & 1;
        int n = nh * 256 + tid;
        float acc = 0.f;
        int k0 = ks * 128;
        #pragma unroll 8
        for (int k = k0; k < k0 + 128; k++)
            acc += bvs[k] * Wo[k * D + n];
        g_bvoP[ks * D + n] = acc;
    } else {
        int o = (b - 616) * 8 + (tid >> 5);
        int lane = tid & 31;
        int hh = o >> 6, ii = o & 63;
        const float4* a4p = (const float4*)(Wkh + (hh * DK + ii) * D);
        const float4* b4p = (const float4*)(bqh + hh * D);
        float acc = 0.f;
        #pragma unroll
        for (int r2 = 0; r2 < 4; r2++) {
            float4 av = a4p[lane + 32*r2], bv2 = b4p[lane + 32*r2];
            acc += av.x*bv2.x + av.y*bv2.y + av.z*bv2.z + av.w*bv2.w;
        }
        #pragma unroll
        for (int off = 16; off; off >>= 1)
            acc += __shfl_xor_sync(0xffffffffu, acc, off);
        if (lane == 0) g_wh[o] = acc;
    }
}

// =================================================================
// K1r: reduce split-K partials + precompute bterm
//   b < 641  : elementwise reductions (qkv / M / Wvo / bvo)
//   b >= 641 : bterm, warp per (h,t): bt = sum_ks kP_ks[t,h,:] . wh[h,:]
// =================================================================
__global__ __launch_bounds__(256) void K1r() {
    int b = blockIdx.x;
    int tid = threadIdx.x;
    if (b < 641) {
        int idx = b * 256 + tid;
        if (idx < 147456) {
            float4 s = ((const float4*)g_qkvP)[idx];
            #pragma unroll
            for (int p = 1; p < 4; p++)
                s = add4(s, ((const float4*)g_qkvP)[idx + p * 147456]);
            ((float4*)g_qkv)[idx] = s;
        } else if (idx < 155648) {
            int i = idx - 147456;
            float4 a = ((const float4*)g_MP)[i];
            float4 b2 = ((const float4*)g_MP)[i + 8192];
            ((float4*)g_M)[i] = add4(a, b2);
        } else if (idx < 163840) {
            int i = idx - 155648;
            float4 a = ((const float4*)g_WvoP)[i];
            float4 b2 = ((const float4*)g_WvoP)[i + 8192];
            ((float4*)g_Wvo)[i] = add4(a, b2);
        } else if (idx < 163968) {
            int i = idx - 163840;
            float4 s = make_float4(0.f, 0.f, 0.f, 0.f);
            #pragma unroll
            for (int p = 0; p < 4; p++)
                s = add4(s, ((const float4*)g_bvoP)[p * 128 + i]);
            ((float4*)g_bvo)[i] = s;
        }
    } else {
        int id = b - 641;                    // 0..383
        int o = id * 8 + (tid >> 5);         // 0..3071 = h*S + t
        int lane = tid & 31;
        int h = o / S, t = o % S;
        float2 whv = *(const float2*)(g_wh + h * DK + 2 * lane);
        float acc = 0.f;
        #pragma unroll
        for (int ks = 0; ks < 4; ks++) {
            float2 kv = *(const float2*)(g_qkvP + (ks * 3 + 1) * (S * D)
                                         + t * D + h * DK + 2 * lane);
            acc += kv.x * whv.x + kv.y * whv.y;
        }
        #pragma unroll
        for (int off = 16; off; off >>= 1)
            acc += __shfl_xor_sync(0xffffffffu, acc, off);
        if (lane == 0) g_bt[o] = acc;
    }
}

// =================================================================
// K2: fused { attn+softmax 16-s tiles, double-buffered K (0..191)
//             | hvo (192..575) }   256 threads
// =================================================================
__global__ __launch_bounds__(256) void K2(float* __restrict__ d_out, long long osz) {
    __shared__ float sm[11216];
    int b = blockIdx.x;
    int tid = threadIdx.x;

    const float* gq = g_qkv;
    const float* gk = g_qkv + S*D;
    const float* gv = g_qkv + 2*S*D;

    if (b < 192) {
        int h = b / 24;
        int s0 = (b % 24) * 16;
        float* sKT0 = sm;              // [64][68]
        float* sKT1 = sm + 4352;       // [64][68]
        float* sQp  = sm + 8704;       // [16][68]
        float* sQ   = sm + 9792;       // [16][65]
        float* sBt  = sm + 10832;      // [384]

        // prologue: M -> sKT0, q -> sQ, bt -> sBt
        #pragma unroll
        for (int r = 0; r < 4; r++) {
            int lin = (r * 256 + tid) * 4;
            int row = lin >> 6, col = lin & 63;
            float4 m4 = *(const float4*)(g_M + h * DK * DK + lin);
            sKT0[row*68+col] = m4.x; sKT0[row*68+col+1] = m4.y;
            sKT0[row*68+col+2] = m4.z; sKT0[row*68+col+3] = m4.w;
        }
        {
            int lin = tid * 4;
            int row = lin >> 6, col = lin & 63;
            float4 q4 = *(const float4*)(gq + (s0 + row) * D + h * DK + col);
            sQ[row*65+col] = q4.x; sQ[row*65+col+1] = q4.y;
            sQ[row*65+col+2] = q4.z; sQ[row*65+col+3] = q4.w;
        }
        #pragma unroll
        for (int i = tid; i < 384; i += 256) sBt[i] = g_bt[h * S + i];
        __syncthreads();

        int tt = tid & 63, kg = tid >> 6;

        // issue chunk-0 K loads early (hide under qprime math)
        float4 kr[4];
        #pragma unroll
        for (int r = 0; r < 4; r++)
            kr[r] = *(const float4*)(gk + tt * D + h * DK + kg * 16 + r * 4);

        // qprime: qp = q @ M  (reads sKT0 + sQ, writes sQp — disjoint regions)
        {
            int sgq = tid >> 4, jg = (tid & 15) * 4;
            float a0 = 0.f, a1 = 0.f, a2 = 0.f, a3 = 0.f;
            #pragma unroll
            for (int i = 0; i < 64; i++) {
                float qv = sQ[sgq*65 + i];
                float4 m4 = *(const float4*)&sKT0[i*68 + jg];
                a0 += qv*m4.x; a1 += qv*m4.y; a2 += qv*m4.z; a3 += qv*m4.w;
            }
            sQp[sgq*68 + jg+0] = a0; sQp[sgq*68 + jg+1] = a1;
            sQp[sgq*68 + jg+2] = a2; sQp[sgq*68 + jg+3] = a3;
        }
        // stage chunk 0 into sKT1
        #pragma unroll
        for (int r = 0; r < 4; r++) {
            int k0 = kg * 16 + r * 4;
            sKT1[(k0+0)*68 + tt] = kr[r].x;
            sKT1[(k0+1)*68 + tt] = kr[r].y;
            sKT1[(k0+2)*68 + tt] = kr[r].z;
            sKT1[(k0+3)*68 + tt] = kr[r].w;
        }
        __syncthreads();

        int sg = tid >> 4, tg = tid & 15;
        int s = s0 + sg;

        float sc[24];
        for (int c = 0; c < 6; c++) {
            float* cbuf = (c & 1) ? sKT0 : sKT1;   // chunk c lives here
            float* nbuf = (c & 1) ? sKT1 : sKT0;   // chunk c+1 staged here
            if (c < 5) {
                #pragma unroll
                for (int r = 0; r < 4; r++) {
                    int k0 = kg * 16 + r * 4;
                    float4 kv = *(const float4*)(gk + ((c+1)*64 + tt) * D + h * DK + k0);
                    nbuf[(k0+0)*68 + tt] = kv.x;
                    nbuf[(k0+1)*68 + tt] = kv.y;
                    nbuf[(k0+2)*68 + tt] = kv.z;
                    nbuf[(k0+3)*68 + tt] = kv.w;
                }
            }
            ull acc0 = 0, acc1 = 0;
            #pragma unroll
            for (int k4 = 0; k4 < 16; k4++) {
                float4 q4 = *(const float4*)&sQp[sg*68 + k4*4];
                float qa[4] = {q4.x, q4.y, q4.z, q4.w};
                #pragma unroll
                for (int kk = 0; kk < 4; kk++) {
                    float4 kv = *(const float4*)&cbuf[(k4*4+kk)*68 + tg*4];
                    ull kA = pk2(kv.x, kv.y), kB = pk2(kv.z, kv.w);
                    ull qp2 = pk2(qa[kk], qa[kk]);
                    acc0 = ffma2(qp2, kA, acc0);
                    acc1 = ffma2(qp2, kB, acc1);
                }
            }
            float2 v0 = upk2(acc0), v1 = upk2(acc1);
            int tb = c * 64 + tg * 4;
            sc[c*4+0] = (v0.x + sBt[tb+0]) * 0.125f;
            sc[c*4+1] = (v0.y + sBt[tb+1]) * 0.125f;
            sc[c*4+2] = (v1.x + sBt[tb+2]) * 0.125f;
            sc[c*4+3] = (v1.y + sBt[tb+3]) * 0.125f;
            __syncthreads();
        }

        float mx = -1e30f;
        #pragma unroll
        for (int i = 0; i < 24; i++) mx = fmaxf(mx, sc[i]);
        #pragma unroll
        for (int o = 1; o < 16; o <<= 1) mx = fmaxf(mx, __shfl_xor_sync(0xffffffffu, mx, o));
        float sum = 0.f;
        #pragma unroll
        for (int i = 0; i < 24; i++) { sc[i] = __expf(sc[i] - mx); sum += sc[i]; }
        #pragma unroll
        for (int o = 1; o < 16; o <<= 1) sum += __shfl_xor_sync(0xffffffffu, sum, o);
        float inv = 1.0f / sum;

        #pragma unroll
        for (int c = 0; c < 6; c++) {
            float a0 = sc[c*4+0] * inv;
            float a1 = sc[c*4+1] * inv;
            float a2 = sc[c*4+2] * inv;
            float a3 = sc[c*4+3] * inv;
            int t = c*64 + tg*4;
            g_attnT[((long long)s * S + t + 0) * H + h] = a0;
            g_attnT[((long long)s * S + t + 1) * H + h] = a1;
            g_attnT[((long long)s * S + t + 2) * H + h] = a2;
            g_attnT[((long long)s * S + t + 3) * H + h] = a3;
            if (h == H - 1) {
                long long oi = (long long)OUT_MAIN + (long long)s * S + t;
                if (oi + 3 < osz)
                    *(float4*)(d_out + oi) = make_float4(a0, a1, a2, a3);
            }
        }
    } else {
        // ---- hvo2[t][h][:] = (vr @ Wvo + bvo) * (1/H) ----
        int p = b - 192;
        int n0 = (p & 7) * 64;
        int q = p >> 3;
        int h = q / 6, t0 = (q % 6) * 64;
        float* sV = sm;          // [64][65]
        float* sW = sm + 4160;   // [64][68]
        #pragma unroll
        for (int r = 0; r < 4; r++) {
            int lin = tid * 4 + r * 1024;
            int row = lin >> 6, col = lin & 63;
            float4 v4 = *(const float4*)(gv + (t0 + row) * D + h * DK + col);
            sV[row*65+col] = v4.x; sV[row*65+col+1] = v4.y;
            sV[row*65+col+2] = v4.z; sV[row*65+col+3] = v4.w;
            float4 w4 = *(const float4*)(g_Wvo + row * D + n0 + col);
            *(float4*)&sW[row*68+col] = w4;
        }
        __syncthreads();
        int tl = tid >> 2, ng = (tid & 3) * 16;
        ull acc[8];
        {
            float4 b0 = *(const float4*)(g_bvo + n0 + ng);
            float4 b1 = *(const float4*)(g_bvo + n0 + ng + 4);
            float4 b2 = *(const float4*)(g_bvo + n0 + ng + 8);
            float4 b3 = *(const float4*)(g_bvo + n0 + ng + 12);
            acc[0] = pk2(b0.x,b0.y); acc[1] = pk2(b0.z,b0.w);
            acc[2] = pk2(b1.x,b1.y); acc[3] = pk2(b1.z,b1.w);
            acc[4] = pk2(b2.x,b2.y); acc[5] = pk2(b2.z,b2.w);
            acc[6] = pk2(b3.x,b3.y); acc[7] = pk2(b3.z,b3.w);
        }
        #pragma unroll
        for (int i = 0; i < 64; i++) {
            float vv = sV[tl*65 + i];
            ull vp = pk2(vv, vv);
            const float* wr = &sW[i*68 + ng];
            float4 wA = *(const float4*)wr;
            float4 wB = *(const float4*)(wr + 4);
            float4 wC = *(const float4*)(wr + 8);
            float4 wD = *(const float4*)(wr + 12);
            acc[0] = ffma2(vp, pk2(wA.x, wA.y), acc[0]);
            acc[1] = ffma2(vp, pk2(wA.z, wA.w), acc[1]);
            acc[2] = ffma2(vp, pk2(wB.x, wB.y), acc[2]);
            acc[3] = ffma2(vp, pk2(wB.z, wB.w), acc[3]);
            acc[4] = ffma2(vp, pk2(wC.x, wC.y), acc[4]);
            acc[5] = ffma2(vp, pk2(wC.z, wC.w), acc[5]);
            acc[6] = ffma2(vp, pk2(wD.x, wD.y), acc[6]);
            acc[7] = ffma2(vp, pk2(wD.z, wD.w), acc[7]);
        }
        int t = t0 + tl;
        #pragma unroll
        for (int rq = 0; rq < 4; rq++) {
            float2 lo = upk2(acc[rq*2]), hi = upk2(acc[rq*2+1]);
            float4 o4 = make_float4(lo.x*0.125f, lo.y*0.125f,
                                    hi.x*0.125f, hi.y*0.125f);
            *(float4*)(g_hvo2 + (t * H + h) * D + n0 + ng + rq*4) = o4;
        }
    }
}

// =================================================================
// K4: out[s,t,:] = bo + sum_h attnT[s,t,h] * hvo2[t,h,:] (frozen)
// =================================================================
__global__ __launch_bounds__(256, 4) void K4(float* __restrict__ d_out,
                                             const float* __restrict__ bo,
                                             long long osz) {
    __shared__ float sA[32*2*8];   // [s][t][h] = 512 floats
    int b = blockIdx.x;
    int t0 = (b % 192) * 2;
    int s0 = (b / 192) * 96;
    int tid = threadIdx.x;
    int dl = (tid & 127) * 4, tq = tid >> 7;
    int t = t0 + tq;

    ull hp[8][2];
    #pragma unroll
    for (int hh = 0; hh < 8; hh++) {
        float4 a = *(const float4*)(g_hvo2 + (t * H + hh) * D + dl);
        hp[hh][0] = pk2(a.x, a.y); hp[hh][1] = pk2(a.z, a.w);
    }
    float4 bA = *(const float4*)(bo + dl);
    ull bop0 = pk2(bA.x, bA.y), bop1 = pk2(bA.z, bA.w);

    for (int ch = 0; ch < 3; ch++) {
        int sb = s0 + ch * 32;
        if (tid < 128) {    // stage attn [32 s][2 t][8 h] = 128 float4
            int s = tid >> 2, rem = tid & 3;
            int tt2 = rem >> 1, half = rem & 1;
            *(float4*)&sA[s*16 + tt2*8 + half*4] =
                *(const float4*)(g_attnT + ((long long)(sb+s)*S + t0+tt2)*H + half*4);
        }
        __syncthreads();
        long long oi = ((long long)sb * S + t) * D + dl;
        #pragma unroll 4
        for (int s = 0; s < 32; s++) {
            const float* wb = &sA[s*16 + tq*8];
            float4 wa = *(const float4*)wb;
            float4 wc = *(const float4*)(wb + 4);
            ull w0 = pk2(wa.x,wa.x), w1 = pk2(wa.y,wa.y);
            ull w2 = pk2(wa.z,wa.z), w3 = pk2(wa.w,wa.w);
            ull w4 = pk2(wc.x,wc.x), w5 = pk2(wc.y,wc.y);
            ull w6 = pk2(wc.z,wc.z), w7 = pk2(wc.w,wc.w);
            ull acc0 = bop0, acc1 = bop1;
            acc0 = ffma2(w0, hp[0][0], acc0); acc1 = ffma2(w0, hp[0][1], acc1);
            acc0 = ffma2(w1, hp[1][0], acc0); acc1 = ffma2(w1, hp[1][1], acc1);
            acc0 = ffma2(w2, hp[2][0], acc0); acc1 = ffma2(w2, hp[2][1], acc1);
            acc0 = ffma2(w3, hp[3][0], acc0); acc1 = ffma2(w3, hp[3][1], acc1);
            acc0 = ffma2(w4, hp[4][0], acc0); acc1 = ffma2(w4, hp[4][1], acc1);
            acc0 = ffma2(w5, hp[5][0], acc0); acc1 = ffma2(w5, hp[5][1], acc1);
            acc0 = ffma2(w6, hp[6][0], acc0); acc1 = ffma2(w6, hp[6][1], acc1);
            acc0 = ffma2(w7, hp[7][0], acc0); acc1 = ffma2(w7, hp[7][1], acc1);
            float2 r0 = upk2(acc0), r1 = upk2(acc1);
            if (oi + 3 < osz)
                __stcs((float4*)(d_out + oi), make_float4(r0.x, r0.y, r1.x, r1.y));
            oi += (long long)S * D;
        }
        __syncthreads();
    }
}

extern "C" void kernel_launch(void* const* d_in, const int* in_sizes, int n_in,
                              void* d_out, int out_size) {
    const float* x   = (const float*)d_in[0];
    const float* Wq  = (const float*)d_in[1];
    const float* bq  = (const float*)d_in[2];
    const float* Wk  = (const float*)d_in[3];
    const float* bk  = (const float*)d_in[4];
    const float* Wv  = (const float*)d_in[5];
    const float* bv  = (const float*)d_in[6];
    const float* Wqh = (const float*)d_in[7];
    const float* bqh = (const float*)d_in[8];
    const float* Wkh = (const float*)d_in[9];
    const float* Wvs = (const float*)d_in[11];
    const float* bvs = (const float*)d_in[12];
    const float* Wo  = (const float*)d_in[13];
    const float* bo  = (const float*)d_in[14];
    float* out = (float*)d_out;
    long long osz = (long long)out_size;

    K1 <<<624, 256>>>(x, Wq, bq, Wk, bk, Wv, bv, Wqh, Wkh, Wvs, bvs, bqh, Wo);
    K1r<<<1025, 256>>>();
    K2 <<<576, 256>>>(out, osz);
    K4 <<<768, 256>>>(out, bo, osz);
}

// round 14
// speedup vs baseline: 1.0916x; 1.0070x over previous
#include <cuda_runtime.h>

#define S 384
#define D 512
#define H 8
#define DK 64
#define OUT_MAIN (S*S*D)   // 75497472

typedef unsigned long long ull;

__device__ __forceinline__ ull ffma2(ull a, ull b, ull c) {
    ull d;
    asm("fma.rn.f32x2 %0, %1, %2, %3;" : "=l"(d) : "l"(a), "l"(b), "l"(c));
    return d;
}
__device__ __forceinline__ ull pk2(float lo, float hi) {
    ull d; asm("mov.b64 %0, {%1, %2};" : "=l"(d) : "f"(lo), "f"(hi)); return d;
}
__device__ __forceinline__ float2 upk2(ull v) {
    float lo, hi; asm("mov.b64 {%0, %1}, %2;" : "=f"(lo), "=f"(hi) : "l"(v));
    return make_float2(lo, hi);
}
__device__ __forceinline__ float4 add4(float4 a, float4 b) {
    return make_float4(a.x+b.x, a.y+b.y, a.z+b.z, a.w+b.w);
}

// ---------------- scratch ----------------
__device__ float g_qkvP[4*3*S*D];    // split-K partials [ks][op][S*D]
__device__ float g_WvoP[2*DK*D];
__device__ float g_MP[2*H*DK*DK];
__device__ float g_bvoP[4*D];
__device__ float g_qkv[3*S*D];       // reduced: q | k | v
__device__ float g_M[H*DK*DK];
__device__ float g_Wvo[DK*D];
__device__ float g_bvo[D];
__device__ float g_wh[H*DK];
__device__ float g_bt[H*S];          // precomputed bterm
__device__ float g_hvo2[S*H*D];      // [t][h][d], pre-scaled by 1/H
__device__ float g_attnT[S*S*H];     // [s][t][h]

// =================================================================
// K1: split-K double-buffered f32x2 GEMM path
// (one __syncthreads per k-chunk — trailing sync removed; safe with
//  2 buffers since stage(c+1)'s buffer was last read by compute(c-1),
//  which every warp finished before passing sync(c))
// =================================================================
__global__ __launch_bounds__(256) void K1(
    const float* __restrict__ x,
    const float* __restrict__ Wq, const float* __restrict__ bq,
    const float* __restrict__ Wk, const float* __restrict__ bk,
    const float* __restrict__ Wv, const float* __restrict__ bv,
    const float* __restrict__ Wqh, const float* __restrict__ Wkh,
    const float* __restrict__ Wvs, const float* __restrict__ bvs,
    const float* __restrict__ bqh, const float* __restrict__ Wo)
{
    __shared__ float sm[6400];
    int b = blockIdx.x;
    int tid = threadIdx.x;

    if (b < 608) {
        const float* Ap; const float* Wp; const float* biasp = 0; float* outp;
        int m0 = 0, n0 = 0, ldo, kbase, nchunks; bool transB = false;
        if (b < 576) {
            int tile = b >> 2; int ks = b & 3;
            int op = tile / 48, r = tile % 48;
            m0 = (r % 6) * 64; n0 = (r / 6) * 64;
            Ap = x;
            if (op == 0)      { Wp = Wq; biasp = bq; }
            else if (op == 1) { Wp = Wk; biasp = bk; }
            else              { Wp = Wv; biasp = bv; }
            if (ks) biasp = 0;
            outp = g_qkvP + (ks * 3 + op) * S * D;
            ldo = D; kbase = ks * 128; nchunks = 8;
        } else if (b < 592) {
            int nt = (b - 576) >> 1; int ks = (b - 576) & 1;
            n0 = nt * 64;
            Ap = Wvs; Wp = Wo; outp = g_WvoP + ks * DK * D; ldo = D;
            kbase = ks * 256; nchunks = 16;
        } else {
            int h = (b - 592) >> 1; int ks = (b - 592) & 1;
            Ap = Wqh + h * DK * D; Wp = Wkh + h * DK * D;
            outp = g_MP + ks * H * DK * DK + h * DK * DK; ldo = DK; transB = true;
            kbase = ks * 256; nchunks = 16;
        }

        float* sA = sm;          // [2][16][132] duplicated pairs
        float* sB = sm + 4224;   // [2][16][68]

        int ma  = tid >> 2, ka4 = (tid & 3) * 4;
        int kb  = tid >> 4, nb4 = (tid & 15) * 4;
        int tm  = (tid >> 4) * 4, tn = (tid & 15) * 4;

        float4 a4 = *(const float4*)(Ap + (m0 + ma) * D + kbase + ka4);
        float4 b4;
        if (!transB) b4 = *(const float4*)(Wp + (kbase + kb) * D + n0 + nb4);
        else         b4 = *(const float4*)(Wp + ma * D + kbase + ka4);

        ull acc[4][2] = {};
        for (int c = 0; c < nchunks; c++) {
            int buf = c & 1;
            float* sAc = sA + buf * 2112;
            float* sBc = sB + buf * 1088;
            {
                *(float2*)&sAc[(ka4+0)*132 + 2*ma] = make_float2(a4.x, a4.x);
                *(float2*)&sAc[(ka4+1)*132 + 2*ma] = make_float2(a4.y, a4.y);
                *(float2*)&sAc[(ka4+2)*132 + 2*ma] = make_float2(a4.z, a4.z);
                *(float2*)&sAc[(ka4+3)*132 + 2*ma] = make_float2(a4.w, a4.w);
                if (!transB) {
                    *(float4*)&sBc[kb*68 + nb4] = b4;
                } else {
                    sBc[(ka4+0)*68 + ma] = b4.x;
                    sBc[(ka4+1)*68 + ma] = b4.y;
                    sBc[(ka4+2)*68 + ma] = b4.z;
                    sBc[(ka4+3)*68 + ma] = b4.w;
                }
            }
            __syncthreads();
            if (c < nchunks - 1) {
                int k0 = kbase + (c + 1) * 16;
                a4 = *(const float4*)(Ap + (m0 + ma) * D + k0 + ka4);
                if (!transB) b4 = *(const float4*)(Wp + (k0 + kb) * D + n0 + nb4);
                else         b4 = *(const float4*)(Wp + ma * D + k0 + ka4);
            }
            #pragma unroll
            for (int k2 = 0; k2 < 16; k2++) {
                ull pb0 = *(const ull*)&sBc[k2*68 + tn];
                ull pb1 = *(const ull*)&sBc[k2*68 + tn + 2];
                ull pa0 = *(const ull*)&sAc[k2*132 + 2*tm];
                ull pa1 = *(const ull*)&sAc[k2*132 + 2*tm + 2];
                ull pa2 = *(const ull*)&sAc[k2*132 + 2*tm + 4];
                ull pa3 = *(const ull*)&sAc[k2*132 + 2*tm + 6];
                acc[0][0] = ffma2(pa0, pb0, acc[0][0]); acc[0][1] = ffma2(pa0, pb1, acc[0][1]);
                acc[1][0] = ffma2(pa1, pb0, acc[1][0]); acc[1][1] = ffma2(pa1, pb1, acc[1][1]);
                acc[2][0] = ffma2(pa2, pb0, acc[2][0]); acc[2][1] = ffma2(pa2, pb1, acc[2][1]);
                acc[3][0] = ffma2(pa3, pb0, acc[3][0]); acc[3][1] = ffma2(pa3, pb1, acc[3][1]);
            }
            // no trailing sync: next iteration stages the other buffer
        }
        float4 bias4 = make_float4(0.f, 0.f, 0.f, 0.f);
        if (biasp) bias4 = *(const float4*)(biasp + n0 + tn);
        #pragma unroll
        for (int i = 0; i < 4; i++) {
            float2 lo = upk2(acc[i][0]), hi = upk2(acc[i][1]);
            float4 o4 = make_float4(lo.x + bias4.x, lo.y + bias4.y,
                                    hi.x + bias4.z, hi.y + bias4.w);
            *(float4*)(outp + (m0 + tm + i) * ldo + n0 + tn) = o4;
        }
    } else if (b < 616) {
        int p = b - 608;
        int ks = p >> 1, nh = p & 1;
        int n = nh * 256 + tid;
        float acc = 0.f;
        int k0 = ks * 128;
        #pragma unroll 8
        for (int k = k0; k < k0 + 128; k++)
            acc += bvs[k] * Wo[k * D + n];
        g_bvoP[ks * D + n] = acc;
    } else {
        int o = (b - 616) * 8 + (tid >> 5);
        int lane = tid & 31;
        int hh = o >> 6, ii = o & 63;
        const float4* a4p = (const float4*)(Wkh + (hh * DK + ii) * D);
        const float4* b4p = (const float4*)(bqh + hh * D);
        float acc = 0.f;
        #pragma unroll
        for (int r2 = 0; r2 < 4; r2++) {
            float4 av = a4p[lane + 32*r2], bv2 = b4p[lane + 32*r2];
            acc += av.x*bv2.x + av.y*bv2.y + av.z*bv2.z + av.w*bv2.w;
        }
        #pragma unroll
        for (int off = 16; off; off >>= 1)
            acc += __shfl_xor_sync(0xffffffffu, acc, off);
        if (lane == 0) g_wh[o] = acc;
    }
}

// =================================================================
// K1r: reduce split-K partials + precompute bterm (frozen)
// =================================================================
__global__ __launch_bounds__(256) void K1r() {
    int b = blockIdx.x;
    int tid = threadIdx.x;
    if (b < 641) {
        int idx = b * 256 + tid;
        if (idx < 147456) {
            float4 s = ((const float4*)g_qkvP)[idx];
            #pragma unroll
            for (int p = 1; p < 4; p++)
                s = add4(s, ((const float4*)g_qkvP)[idx + p * 147456]);
            ((float4*)g_qkv)[idx] = s;
        } else if (idx < 155648) {
            int i = idx - 147456;
            float4 a = ((const float4*)g_MP)[i];
            float4 b2 = ((const float4*)g_MP)[i + 8192];
            ((float4*)g_M)[i] = add4(a, b2);
        } else if (idx < 163840) {
            int i = idx - 155648;
            float4 a = ((const float4*)g_WvoP)[i];
            float4 b2 = ((const float4*)g_WvoP)[i + 8192];
            ((float4*)g_Wvo)[i] = add4(a, b2);
        } else if (idx < 163968) {
            int i = idx - 163840;
            float4 s = make_float4(0.f, 0.f, 0.f, 0.f);
            #pragma unroll
            for (int p = 0; p < 4; p++)
                s = add4(s, ((const float4*)g_bvoP)[p * 128 + i]);
            ((float4*)g_bvo)[i] = s;
        }
    } else {
        int id = b - 641;                    // 0..383
        int o = id * 8 + (tid >> 5);         // 0..3071 = h*S + t
        int lane = tid & 31;
        int h = o / S, t = o % S;
        float2 whv = *(const float2*)(g_wh + h * DK + 2 * lane);
        float acc = 0.f;
        #pragma unroll
        for (int ks = 0; ks < 4; ks++) {
            float2 kv = *(const float2*)(g_qkvP + (ks * 3 + 1) * (S * D)
                                         + t * D + h * DK + 2 * lane);
            acc += kv.x * whv.x + kv.y * whv.y;
        }
        #pragma unroll
        for (int off = 16; off; off >>= 1)
            acc += __shfl_xor_sync(0xffffffffu, acc, off);
        if (lane == 0) g_bt[o] = acc;
    }
}

// =================================================================
// K2: fused { attn+softmax 16-s tiles, double-buffered K (0..191)
//             | hvo (192..575) }   256 threads  (frozen from R13)
// =================================================================
__global__ __launch_bounds__(256) void K2(float* __restrict__ d_out, long long osz) {
    __shared__ float sm[11216];
    int b = blockIdx.x;
    int tid = threadIdx.x;

    const float* gq = g_qkv;
    const float* gk = g_qkv + S*D;
    const float* gv = g_qkv + 2*S*D;

    if (b < 192) {
        int h = b / 24;
        int s0 = (b % 24) * 16;
        float* sKT0 = sm;              // [64][68]
        float* sKT1 = sm + 4352;       // [64][68]
        float* sQp  = sm + 8704;       // [16][68]
        float* sQ   = sm + 9792;       // [16][65]
        float* sBt  = sm + 10832;      // [384]

        #pragma unroll
        for (int r = 0; r < 4; r++) {
            int lin = (r * 256 + tid) * 4;
            int row = lin >> 6, col = lin & 63;
            float4 m4 = *(const float4*)(g_M + h * DK * DK + lin);
            sKT0[row*68+col] = m4.x; sKT0[row*68+col+1] = m4.y;
            sKT0[row*68+col+2] = m4.z; sKT0[row*68+col+3] = m4.w;
        }
        {
            int lin = tid * 4;
            int row = lin >> 6, col = lin & 63;
            float4 q4 = *(const float4*)(gq + (s0 + row) * D + h * DK + col);
            sQ[row*65+col] = q4.x; sQ[row*65+col+1] = q4.y;
            sQ[row*65+col+2] = q4.z; sQ[row*65+col+3] = q4.w;
        }
        #pragma unroll
        for (int i = tid; i < 384; i += 256) sBt[i] = g_bt[h * S + i];
        __syncthreads();

        int tt = tid & 63, kg = tid >> 6;

        float4 kr[4];
        #pragma unroll
        for (int r = 0; r < 4; r++)
            kr[r] = *(const float4*)(gk + tt * D + h * DK + kg * 16 + r * 4);

        {
            int sgq = tid >> 4, jg = (tid & 15) * 4;
            float a0 = 0.f, a1 = 0.f, a2 = 0.f, a3 = 0.f;
            #pragma unroll
            for (int i = 0; i < 64; i++) {
                float qv = sQ[sgq*65 + i];
                float4 m4 = *(const float4*)&sKT0[i*68 + jg];
                a0 += qv*m4.x; a1 += qv*m4.y; a2 += qv*m4.z; a3 += qv*m4.w;
            }
            sQp[sgq*68 + jg+0] = a0; sQp[sgq*68 + jg+1] = a1;
            sQp[sgq*68 + jg+2] = a2; sQp[sgq*68 + jg+3] = a3;
        }
        #pragma unroll
        for (int r = 0; r < 4; r++) {
            int k0 = kg * 16 + r * 4;
            sKT1[(k0+0)*68 + tt] = kr[r].x;
            sKT1[(k0+1)*68 + tt] = kr[r].y;
            sKT1[(k0+2)*68 + tt] = kr[r].z;
            sKT1[(k0+3)*68 + tt] = kr[r].w;
        }
        __syncthreads();

        int sg = tid >> 4, tg = tid & 15;
        int s = s0 + sg;

        float sc[24];
        for (int c = 0; c < 6; c++) {
            float* cbuf = (c & 1) ? sKT0 : sKT1;
            float* nbuf = (c & 1) ? sKT1 : sKT0;
            if (c < 5) {
                #pragma unroll
                for (int r = 0; r < 4; r++) {
                    int k0 = kg * 16 + r * 4;
                    float4 kv = *(const float4*)(gk + ((c+1)*64 + tt) * D + h * DK + k0);
                    nbuf[(k0+0)*68 + tt] = kv.x;
                    nbuf[(k0+1)*68 + tt] = kv.y;
                    nbuf[(k0+2)*68 + tt] = kv.z;
                    nbuf[(k0+3)*68 + tt] = kv.w;
                }
            }
            ull acc0 = 0, acc1 = 0;
            #pragma unroll
            for (int k4 = 0; k4 < 16; k4++) {
                float4 q4 = *(const float4*)&sQp[sg*68 + k4*4];
                float qa[4] = {q4.x, q4.y, q4.z, q4.w};
                #pragma unroll
                for (int kk = 0; kk < 4; kk++) {
                    float4 kv = *(const float4*)&cbuf[(k4*4+kk)*68 + tg*4];
                    ull kA = pk2(kv.x, kv.y), kB = pk2(kv.z, kv.w);
                    ull qp2 = pk2(qa[kk], qa[kk]);
                    acc0 = ffma2(qp2, kA, acc0);
                    acc1 = ffma2(qp2, kB, acc1);
                }
            }
            float2 v0 = upk2(acc0), v1 = upk2(acc1);
            int tb = c * 64 + tg * 4;
            sc[c*4+0] = (v0.x + sBt[tb+0]) * 0.125f;
            sc[c*4+1] = (v0.y + sBt[tb+1]) * 0.125f;
            sc[c*4+2] = (v1.x + sBt[tb+2]) * 0.125f;
            sc[c*4+3] = (v1.y + sBt[tb+3]) * 0.125f;
            __syncthreads();
        }

        float mx = -1e30f;
        #pragma unroll
        for (int i = 0; i < 24; i++) mx = fmaxf(mx, sc[i]);
        #pragma unroll
        for (int o = 1; o < 16; o <<= 1) mx = fmaxf(mx, __shfl_xor_sync(0xffffffffu, mx, o));
        float sum = 0.f;
        #pragma unroll
        for (int i = 0; i < 24; i++) { sc[i] = __expf(sc[i] - mx); sum += sc[i]; }
        #pragma unroll
        for (int o = 1; o < 16; o <<= 1) sum += __shfl_xor_sync(0xffffffffu, sum, o);
        float inv = 1.0f / sum;

        #pragma unroll
        for (int c = 0; c < 6; c++) {
            float a0 = sc[c*4+0] * inv;
            float a1 = sc[c*4+1] * inv;
            float a2 = sc[c*4+2] * inv;
            float a3 = sc[c*4+3] * inv;
            int t = c*64 + tg*4;
            g_attnT[((long long)s * S + t + 0) * H + h] = a0;
            g_attnT[((long long)s * S + t + 1) * H + h] = a1;
            g_attnT[((long long)s * S + t + 2) * H + h] = a2;
            g_attnT[((long long)s * S + t + 3) * H + h] = a3;
            if (h == H - 1) {
                long long oi = (long long)OUT_MAIN + (long long)s * S + t;
                if (oi + 3 < osz)
                    *(float4*)(d_out + oi) = make_float4(a0, a1, a2, a3);
            }
        }
    } else {
        // ---- hvo2[t][h][:] = (vr @ Wvo + bvo) * (1/H) ----
        int p = b - 192;
        int n0 = (p & 7) * 64;
        int q = p >> 3;
        int h = q / 6, t0 = (q % 6) * 64;
        float* sV = sm;          // [64][65]
        float* sW = sm + 4160;   // [64][68]
        #pragma unroll
        for (int r = 0; r < 4; r++) {
            int lin = tid * 4 + r * 1024;
            int row = lin >> 6, col = lin & 63;
            float4 v4 = *(const float4*)(gv + (t0 + row) * D + h * DK + col);
            sV[row*65+col] = v4.x; sV[row*65+col+1] = v4.y;
            sV[row*65+col+2] = v4.z; sV[row*65+col+3] = v4.w;
            float4 w4 = *(const float4*)(g_Wvo + row * D + n0 + col);
            *(float4*)&sW[row*68+col] = w4;
        }
        __syncthreads();
        int tl = tid >> 2, ng = (tid & 3) * 16;
        ull acc[8];
        {
            float4 b0 = *(const float4*)(g_bvo + n0 + ng);
            float4 b1 = *(const float4*)(g_bvo + n0 + ng + 4);
            float4 b2 = *(const float4*)(g_bvo + n0 + ng + 8);
            float4 b3 = *(const float4*)(g_bvo + n0 + ng + 12);
            acc[0] = pk2(b0.x,b0.y); acc[1] = pk2(b0.z,b0.w);
            acc[2] = pk2(b1.x,b1.y); acc[3] = pk2(b1.z,b1.w);
            acc[4] = pk2(b2.x,b2.y); acc[5] = pk2(b2.z,b2.w);
            acc[6] = pk2(b3.x,b3.y); acc[7] = pk2(b3.z,b3.w);
        }
        #pragma unroll
        for (int i = 0; i < 64; i++) {
            float vv = sV[tl*65 + i];
            ull vp = pk2(vv, vv);
            const float* wr = &sW[i*68 + ng];
            float4 wA = *(const float4*)wr;
            float4 wB = *(const float4*)(wr + 4);
            float4 wC = *(const float4*)(wr + 8);
            float4 wD = *(const float4*)(wr + 12);
            acc[0] = ffma2(vp, pk2(wA.x, wA.y), acc[0]);
            acc[1] = ffma2(vp, pk2(wA.z, wA.w), acc[1]);
            acc[2] = ffma2(vp, pk2(wB.x, wB.y), acc[2]);
            acc[3] = ffma2(vp, pk2(wB.z, wB.w), acc[3]);
            acc[4] = ffma2(vp, pk2(wC.x, wC.y), acc[4]);
            acc[5] = ffma2(vp, pk2(wC.z, wC.w), acc[5]);
            acc[6] = ffma2(vp, pk2(wD.x, wD.y), acc[6]);
            acc[7] = ffma2(vp, pk2(wD.z, wD.w), acc[7]);
        }
        int t = t0 + tl;
        #pragma unroll
        for (int rq = 0; rq < 4; rq++) {
            float2 lo = upk2(acc[rq*2]), hi = upk2(acc[rq*2+1]);
            float4 o4 = make_float4(lo.x*0.125f, lo.y*0.125f,
                                    hi.x*0.125f, hi.y*0.125f);
            *(float4*)(g_hvo2 + (t * H + h) * D + n0 + ng + rq*4) = o4;
        }
    }
}

// =================================================================
// K4: out[s,t,:] = bo + sum_h attnT[s,t,h] * hvo2[t,h,:] (frozen)
// =================================================================
__global__ __launch_bounds__(256, 4) void K4(float* __restrict__ d_out,
                                             const float* __restrict__ bo,
                                             long long osz) {
    __shared__ float sA[32*2*8];   // [s][t][h] = 512 floats
    int b = blockIdx.x;
    int t0 = (b % 192) * 2;
    int s0 = (b / 192) * 96;
    int tid = threadIdx.x;
    int dl = (tid & 127) * 4, tq = tid >> 7;
    int t = t0 + tq;

    ull hp[8][2];
    #pragma unroll
    for (int hh = 0; hh < 8; hh++) {
        float4 a = *(const float4*)(g_hvo2 + (t * H + hh) * D + dl);
        hp[hh][0] = pk2(a.x, a.y); hp[hh][1] = pk2(a.z, a.w);
    }
    float4 bA = *(const float4*)(bo + dl);
    ull bop0 = pk2(bA.x, bA.y), bop1 = pk2(bA.z, bA.w);

    for (int ch = 0; ch < 3; ch++) {
        int sb = s0 + ch * 32;
        if (tid < 128) {    // stage attn [32 s][2 t][8 h] = 128 float4
            int s = tid >> 2, rem = tid & 3;
            int tt2 = rem >> 1, half = rem & 1;
            *(float4*)&sA[s*16 + tt2*8 + half*4] =
                *(const float4*)(g_attnT + ((long long)(sb+s)*S + t0+tt2)*H + half*4);
        }
        __syncthreads();
        long long oi = ((long long)sb * S + t) * D + dl;
        #pragma unroll 4
        for (int s = 0; s < 32; s++) {
            const float* wb = &sA[s*16 + tq*8];
            float4 wa = *(const float4*)wb;
            float4 wc = *(const float4*)(wb + 4);
            ull w0 = pk2(wa.x,wa.x), w1 = pk2(wa.y,wa.y);
            ull w2 = pk2(wa.z,wa.z), w3 = pk2(wa.w,wa.w);
            ull w4 = pk2(wc.x,wc.x), w5 = pk2(wc.y,wc.y);
            ull w6 = pk2(wc.z,wc.z), w7 = pk2(wc.w,wc.w);
            ull acc0 = bop0, acc1 = bop1;
            acc0 = ffma2(w0, hp[0][0], acc0); acc1 = ffma2(w0, hp[0][1], acc1);
            acc0 = ffma2(w1, hp[1][0], acc0); acc1 = ffma2(w1, hp[1][1], acc1);
            acc0 = ffma2(w2, hp[2][0], acc0); acc1 = ffma2(w2, hp[2][1], acc1);
            acc0 = ffma2(w3, hp[3][0], acc0); acc1 = ffma2(w3, hp[3][1], acc1);
            acc0 = ffma2(w4, hp[4][0], acc0); acc1 = ffma2(w4, hp[4][1], acc1);
            acc0 = ffma2(w5, hp[5][0], acc0); acc1 = ffma2(w5, hp[5][1], acc1);
            acc0 = ffma2(w6, hp[6][0], acc0); acc1 = ffma2(w6, hp[6][1], acc1);
            acc0 = ffma2(w7, hp[7][0], acc0); acc1 = ffma2(w7, hp[7][1], acc1);
            float2 r0 = upk2(acc0), r1 = upk2(acc1);
            if (oi + 3 < osz)
                __stcs((float4*)(d_out + oi), make_float4(r0.x, r0.y, r1.x, r1.y));
            oi += (long long)S * D;
        }
        __syncthreads();
    }
}

extern "C" void kernel_launch(void* const* d_in, const int* in_sizes, int n_in,
                              void* d_out, int out_size) {
    const float* x   = (const float*)d_in[0];
    const float* Wq  = (const float*)d_in[1];
    const float* bq  = (const float*)d_in[2];
    const float* Wk  = (const float*)d_in[3];
    const float* bk  = (const float*)d_in[4];
    const float* Wv  = (const float*)d_in[5];
    const float* bv  = (const float*)d_in[6];
    const float* Wqh = (const float*)d_in[7];
    const float* bqh = (const float*)d_in[8];
    const float* Wkh = (const float*)d_in[9];
    const float* Wvs = (const float*)d_in[11];
    const float* bvs = (const float*)d_in[12];
    const float* Wo  = (const float*)d_in[13];
    const float* bo  = (const float*)d_in[14];
    float* out = (float*)d_out;
    long long osz = (long long)out_size;

    K1 <<<624, 256>>>(x, Wq, bq, Wk, bk, Wv, bv, Wqh, Wkh, Wvs, bvs, bqh, Wo);
    K1r<<<1025, 256>>>();
    K2 <<<576, 256>>>(out, osz);
    K4 <<<768, 256>>>(out, bo, osz);
}